// round 2
// baseline (speedup 1.0000x reference)
#include <cuda_runtime.h>
#include <cstdint>

// Problem constants
#define NN 8
#define CC 64
#define FF 256
#define TT 256
#define BB (NN*TT)          // 2048 batches
#define RS 68               // smem row stride in floats (16B-aligned, conflict-free)

typedef unsigned long long u64;

// 128MB scratch: holds xT [B,F,C] then (in-place, per-CTA safe) y [B,F,C]
__device__ float g_scratch[(size_t)BB * FF * CC];

// ---------------- packed fp32x2 helpers (full fp32 precision, 2x throughput) ----------
static __device__ __forceinline__ u64 pk2(float lo, float hi) {
    u64 r; asm("mov.b64 %0,{%1,%2};" : "=l"(r) : "f"(lo), "f"(hi)); return r;
}
static __device__ __forceinline__ void upk2(u64 a, float& lo, float& hi) {
    asm("mov.b64 {%0,%1},%2;" : "=f"(lo), "=f"(hi) : "l"(a));
}
static __device__ __forceinline__ u64 f2fma(u64 a, u64 b, u64 c) {
    u64 d; asm("fma.rn.f32x2 %0,%1,%2,%3;" : "=l"(d) : "l"(a), "l"(b), "l"(c)); return d;
}
static __device__ __forceinline__ u64 f2mul(u64 a, u64 b) {
    u64 d; asm("mul.rn.f32x2 %0,%1,%2;" : "=l"(d) : "l"(a), "l"(b)); return d;
}
static __device__ __forceinline__ u64 f2add(u64 a, u64 b) {
    u64 d; asm("add.rn.f32x2 %0,%1,%2;" : "=l"(d) : "l"(a), "l"(b)); return d;
}

// ---------------- kernel 1: transpose [N,C,F,T] -> xT [N*T, F, C] ----------------
// grid (T/32, C/32, N*F), block (32,8)
__global__ void k_tin(const float* __restrict__ in) {
    __shared__ float tile[32][33];
    int n = blockIdx.z >> 8, f = blockIdx.z & 255;
    int c0 = blockIdx.y << 5, t0 = blockIdx.x << 5;
    int tx = threadIdx.x, ty = threadIdx.y;
    int base_in = ((n * 64) * 256 + f) * 256;          // + c*65536 + t
#pragma unroll
    for (int i = 0; i < 32; i += 8) {
        tile[ty + i][tx] = in[base_in + (c0 + ty + i) * 65536 + t0 + tx];
    }
    __syncthreads();
    int base_out = n * (256 * 16384) + f * 64;          // + t*16384 + c
#pragma unroll
    for (int i = 0; i < 32; i += 8) {
        g_scratch[base_out + (t0 + ty + i) * 16384 + c0 + tx] = tile[tx][ty + i];
    }
}

// ---------------- kernel 3: y [B,F,C] -> out [N,C,F,T] (+ residual) ----------------
__global__ void k_tout(const float* __restrict__ in, float* __restrict__ out) {
    __shared__ float tile[32][33];
    int n = blockIdx.z >> 8, f = blockIdx.z & 255;
    int c0 = blockIdx.y << 5, t0 = blockIdx.x << 5;
    int tx = threadIdx.x, ty = threadIdx.y;
    int base_y = n * (256 * 16384) + f * 64;
#pragma unroll
    for (int i = 0; i < 32; i += 8) {
        tile[ty + i][tx] = g_scratch[base_y + (t0 + ty + i) * 16384 + c0 + tx];
    }
    __syncthreads();
    int base_o = ((n * 64) * 256 + f) * 256;
#pragma unroll
    for (int i = 0; i < 32; i += 8) {
        int a = base_o + (c0 + ty + i) * 65536 + t0 + tx;
        out[a] = tile[tx][ty + i] + in[a];
    }
}

// ---------------- fused attention kernel ----------------
// smem layout (floats)
#define OFF_K   (256 * RS)            // 17408
#define OFF_V   (2 * 256 * RS)        // 34816
#define OFF_W   (3 * 256 * RS)        // 52224
#define OFF_G1  (OFF_W + 64 * RS)     // 56576
#define OFF_B1  (OFF_G1 + 64)
#define OFF_G2  (OFF_B1 + 64)
#define OFF_B2  (OFF_G2 + 64)
#define OFF_G3  (OFF_B2 + 64)
#define OFF_B3  (OFF_G3 + 64)
#define OFF_BIAS (OFF_B3 + 64)
#define SMEM_FLOATS (OFF_BIAS + 64)   // 57024
#define SMEM_BYTES  (SMEM_FLOATS * 4) // 228096 < 227KB limit

// stage a 64x64 weight (row-major [out][in]) + bias into smem; caller syncs
static __device__ __forceinline__ void stageW(const float* __restrict__ W,
                                              const float* __restrict__ bias,
                                              float* sw, float* sbias, int tid) {
    for (int i = tid; i < 4096; i += 256) sw[(i >> 6) * RS + (i & 63)] = W[i];
    if (tid < 64) sbias[tid] = bias[tid];
}

// per-thread row GEMM: dst[o] = bias[o] + sum_i h2[i] * W[o][i], o=0..63
static __device__ __forceinline__ void gemm64(const u64* h2, const float* sw,
                                              const float* sbias, float* dst) {
    for (int o = 0; o < 64; o += 4) {
        const ulonglong2* w0 = (const ulonglong2*)(sw + (o + 0) * RS);
        const ulonglong2* w1 = (const ulonglong2*)(sw + (o + 1) * RS);
        const ulonglong2* w2 = (const ulonglong2*)(sw + (o + 2) * RS);
        const ulonglong2* w3 = (const ulonglong2*)(sw + (o + 3) * RS);
        u64 a0 = 0ull, a1 = 0ull, a2 = 0ull, a3 = 0ull;
#pragma unroll
        for (int j = 0; j < 16; j++) {
            ulonglong2 x0 = w0[j], x1 = w1[j], x2 = w2[j], x3 = w3[j];
            u64 hlo = h2[2 * j], hhi = h2[2 * j + 1];
            a0 = f2fma(hlo, x0.x, a0); a1 = f2fma(hlo, x1.x, a1);
            a2 = f2fma(hlo, x2.x, a2); a3 = f2fma(hlo, x3.x, a3);
            a0 = f2fma(hhi, x0.y, a0); a1 = f2fma(hhi, x1.y, a1);
            a2 = f2fma(hhi, x2.y, a2); a3 = f2fma(hhi, x3.y, a3);
        }
        float e0, e1, e2, e3, e4, e5, e6, e7;
        upk2(a0, e0, e1); upk2(a1, e2, e3); upk2(a2, e4, e5); upk2(a3, e6, e7);
        float4 r = make_float4(e0 + e1 + sbias[o],     e2 + e3 + sbias[o + 1],
                               e4 + e5 + sbias[o + 2], e6 + e7 + sbias[o + 3]);
        *reinterpret_cast<float4*>(dst + o) = r;
    }
}

__global__ void __launch_bounds__(256, 1) k_attn(
    const float* __restrict__ Wq, const float* __restrict__ bq,
    const float* __restrict__ Wk, const float* __restrict__ bk,
    const float* __restrict__ Wv, const float* __restrict__ bv,
    const float* __restrict__ g1, const float* __restrict__ b1,
    const float* __restrict__ g2, const float* __restrict__ b2,
    const float* __restrict__ Wt, const float* __restrict__ bt,
    const float* __restrict__ g3, const float* __restrict__ b3,
    const float* __restrict__ alpha)
{
    extern __shared__ float sm[];
    float* sh    = sm;
    float* sk    = sm + OFF_K;
    float* sv    = sm + OFF_V;
    float* sw    = sm + OFF_W;
    float* sg1   = sm + OFF_G1;
    float* sb1   = sm + OFF_B1;
    float* sg2   = sm + OFF_G2;
    float* sb2   = sm + OFF_B2;
    float* sg3   = sm + OFF_G3;
    float* sb3   = sm + OFF_B3;
    float* sbias = sm + OFF_BIAS;

    int tid = threadIdx.x;
    int b = blockIdx.x;
    float* xb = g_scratch + b * 16384;
    float al = __ldg(alpha);

    // ---- Phase A: load x tile + params
    for (int i = tid; i < 16384; i += 256) sh[(i >> 6) * RS + (i & 63)] = xb[i];
    if (tid < 64) {
        sg1[tid] = g1[tid]; sb1[tid] = b1[tid];
        sg2[tid] = g2[tid]; sb2[tid] = b2[tid];
        sg3[tid] = g3[tid]; sb3[tid] = b3[tid];
    }
    __syncthreads();

    // ---- Phase B: LayerNorm1 over C (warp per row, rows strided by 8)
    int lane = tid & 31, wid = tid >> 5;
    {
        float gl0 = sg1[lane], bl0 = sb1[lane], gl1 = sg1[lane + 32], bl1 = sb1[lane + 32];
        for (int r = wid; r < 256; r += 8) {
            float a0 = sh[r * RS + lane], a1 = sh[r * RS + 32 + lane];
            float s = a0 + a1;
#pragma unroll
            for (int o = 16; o; o >>= 1) s += __shfl_xor_sync(0xffffffffu, s, o);
            float mean = s * (1.0f / 64.0f);
            float d0 = a0 - mean, d1 = a1 - mean;
            float qv = d0 * d0 + d1 * d1;
#pragma unroll
            for (int o = 16; o; o >>= 1) qv += __shfl_xor_sync(0xffffffffu, qv, o);
            float rstd = rsqrtf(qv * (1.0f / 64.0f) + 1e-5f);
            sh[r * RS + lane]      = d0 * rstd * gl0 + bl0;
            sh[r * RS + 32 + lane] = d1 * rstd * gl1 + bl1;
        }
    }
    __syncthreads();

    // ---- load this thread's normalized row into registers (packed)
    u64 hr[32];
    {
        const ulonglong2* hp = (const ulonglong2*)(sh + tid * RS);
#pragma unroll
        for (int j = 0; j < 16; j++) { ulonglong2 t = hp[j]; hr[2 * j] = t.x; hr[2 * j + 1] = t.y; }
    }

    // ---- Phase C: K, V, Q GEMMs (weight buffer reused with syncs)
    stageW(Wk, bk, sw, sbias, tid); __syncthreads();
    gemm64(hr, sw, sbias, sk + tid * RS); __syncthreads();

    stageW(Wv, bv, sw, sbias, tid); __syncthreads();
    gemm64(hr, sw, sbias, sv + tid * RS); __syncthreads();

    stageW(Wq, bq, sw, sbias, tid); __syncthreads();
    gemm64(hr, sw, sbias, sh + tid * RS);   // q into own (now free) h row
    u64 q2[32];
    {
        const ulonglong2* qp = (const ulonglong2*)(sh + tid * RS);
#pragma unroll
        for (int j = 0; j < 16; j++) { ulonglong2 t = qp[j]; q2[2 * j] = t.x; q2[2 * j + 1] = t.y; }
    }
    __syncthreads();

    // stage Wt/bt now (attention doesn't touch sw/sbias)
    stageW(Wt, bt, sw, sbias, tid); __syncthreads();

    // ---- Phase D: attention row (online softmax with lazy rescale)
    u64 acc[32];
#pragma unroll
    for (int j = 0; j < 32; j++) acc[j] = 0ull;
    float m = -1e30f, l = 0.0f;

#pragma unroll 2
    for (int s = 0; s < 256; s++) {
        const ulonglong2* kp = (const ulonglong2*)(sk + s * RS);
        u64 dA = 0ull, dB = 0ull, dC = 0ull, dD = 0ull;
#pragma unroll
        for (int j = 0; j < 16; j += 4) {
            ulonglong2 k0 = kp[j], k1 = kp[j + 1], k2 = kp[j + 2], k3 = kp[j + 3];
            dA = f2fma(q2[2 * j],     k0.x, dA); dB = f2fma(q2[2 * j + 2], k1.x, dB);
            dC = f2fma(q2[2 * j + 4], k2.x, dC); dD = f2fma(q2[2 * j + 6], k3.x, dD);
            dA = f2fma(q2[2 * j + 1], k0.y, dA); dB = f2fma(q2[2 * j + 3], k1.y, dB);
            dC = f2fma(q2[2 * j + 5], k2.y, dC); dD = f2fma(q2[2 * j + 7], k3.y, dD);
        }
        u64 dS = f2add(f2add(dA, dB), f2add(dC, dD));
        float dl, dh; upk2(dS, dl, dh);
        float sc = (dl + dh) * 0.125f;

        if (sc > m) {                       // rare after warm-up (~ln(256) times)
            float corr = __expf(m - sc);    // m=-1e30 first time -> corr=0
            l *= corr;
            u64 c2 = pk2(corr, corr);
#pragma unroll
            for (int j = 0; j < 32; j++) acc[j] = f2mul(acc[j], c2);
            m = sc;
        }
        float p = __expf(sc - m);
        l += p;
        u64 p2 = pk2(p, p);
        const ulonglong2* vp = (const ulonglong2*)(sv + s * RS);
#pragma unroll
        for (int j = 0; j < 16; j++) {
            ulonglong2 vv = vp[j];
            acc[2 * j]     = f2fma(p2, vv.x, acc[2 * j]);
            acc[2 * j + 1] = f2fma(p2, vv.y, acc[2 * j + 1]);
        }
    }

    // ---- Phase E: normalize + LayerNorm2 over H (thread-local)
    float wvv[64];
    {
        float inv = 1.0f / l;
#pragma unroll
        for (int j = 0; j < 32; j++) {
            float lo, hi; upk2(acc[j], lo, hi);
            wvv[2 * j] = lo * inv; wvv[2 * j + 1] = hi * inv;
        }
        float s2 = 0.0f;
#pragma unroll
        for (int i = 0; i < 64; i++) s2 += wvv[i];
        float mean = s2 * (1.0f / 64.0f);
        float vs = 0.0f;
#pragma unroll
        for (int i = 0; i < 64; i++) { float d = wvv[i] - mean; vs += d * d; }
        float rstd = rsqrtf(vs * (1.0f / 64.0f) + 1e-5f);
#pragma unroll
        for (int j = 0; j < 32; j++) {
            float v0 = (wvv[2 * j]     - mean) * rstd * sg2[2 * j]     + sb2[2 * j];
            float v1 = (wvv[2 * j + 1] - mean) * rstd * sg2[2 * j + 1] + sb2[2 * j + 1];
            acc[j] = pk2(v0, v1);           // reuse acc as packed LN2 output
        }
    }

    // ---- Phase F: output GEMM (Wt), then LN3 + PReLU, write back
    gemm64(acc, sw, sbias, sh + tid * RS);
    {
        const float4* op = (const float4*)(sh + tid * RS);
        float ov[64];
#pragma unroll
        for (int j = 0; j < 16; j++) {
            float4 t4 = op[j];
            ov[4 * j] = t4.x; ov[4 * j + 1] = t4.y; ov[4 * j + 2] = t4.z; ov[4 * j + 3] = t4.w;
        }
        float s3 = 0.0f;
#pragma unroll
        for (int i = 0; i < 64; i++) s3 += ov[i];
        float mean = s3 * (1.0f / 64.0f);
        float vs = 0.0f;
#pragma unroll
        for (int i = 0; i < 64; i++) { float d = ov[i] - mean; vs += d * d; }
        float rstd = rsqrtf(vs * (1.0f / 64.0f) + 1e-5f);
        float4* opw = (float4*)(sh + tid * RS);
#pragma unroll
        for (int j = 0; j < 16; j++) {
            float4 r;
            float e;
            e = (ov[4 * j]     - mean) * rstd * sg3[4 * j]     + sb3[4 * j];     r.x = (e >= 0.0f) ? e : al * e;
            e = (ov[4 * j + 1] - mean) * rstd * sg3[4 * j + 1] + sb3[4 * j + 1]; r.y = (e >= 0.0f) ? e : al * e;
            e = (ov[4 * j + 2] - mean) * rstd * sg3[4 * j + 2] + sb3[4 * j + 2]; r.z = (e >= 0.0f) ? e : al * e;
            e = (ov[4 * j + 3] - mean) * rstd * sg3[4 * j + 3] + sb3[4 * j + 3]; r.w = (e >= 0.0f) ? e : al * e;
            opw[j] = r;
        }
    }
    __syncthreads();
    // coalesced write-back into the scratch (same region this CTA read in Phase A)
    for (int i = tid; i < 16384; i += 256) xb[i] = sh[(i >> 6) * RS + (i & 63)];
}

// ---------------- launch ----------------
extern "C" void kernel_launch(void* const* d_in, const int* in_sizes, int n_in,
                              void* d_out, int out_size) {
    (void)in_sizes; (void)n_in; (void)out_size;
    const float* inputs = (const float*)d_in[0];
    const float* Wq = (const float*)d_in[1];
    const float* bq = (const float*)d_in[2];
    const float* Wk = (const float*)d_in[3];
    const float* bk = (const float*)d_in[4];
    const float* Wv = (const float*)d_in[5];
    const float* bv = (const float*)d_in[6];
    const float* g1 = (const float*)d_in[7];
    const float* b1 = (const float*)d_in[8];
    const float* g2 = (const float*)d_in[9];
    const float* b2 = (const float*)d_in[10];
    const float* Wt = (const float*)d_in[11];
    const float* bt = (const float*)d_in[12];
    const float* g3 = (const float*)d_in[13];
    const float* b3 = (const float*)d_in[14];
    const float* alpha = (const float*)d_in[15];
    float* out = (float*)d_out;

    cudaFuncSetAttribute(k_attn, cudaFuncAttributeMaxDynamicSharedMemorySize, SMEM_BYTES);

    dim3 tgrid(8, 2, NN * FF);   // (T/32, C/32, N*F)
    dim3 tblk(32, 8);
    k_tin<<<tgrid, tblk>>>(inputs);
    k_attn<<<BB, 256, SMEM_BYTES>>>(Wq, bq, Wk, bk, Wv, bv, g1, b1, g2, b2,
                                    Wt, bt, g3, b3, alpha);
    k_tout<<<tgrid, tblk>>>(inputs, out);
}

// round 5
// speedup vs baseline: 2.1624x; 2.1624x over previous
#include <cuda_runtime.h>
#include <cstdint>

typedef uint32_t u32;
#define BB 2048

__device__ float g_scratch[(size_t)BB * 256 * 64];

// ---- smem regions (bytes). 256-row f16 tiles: 128B/row SW128-swizzled, hi + lo halves.
#define R_H   0          // H tile (hi), lo at +32768
#define R_K   65536
#define R_V   131072
#define R_W   196608     // 64-row weight tile (hi), lo at +8192
#define R_QN  212992     // 256 floats: ||q_row||
#define R_KM  214016     // 8 floats: per-warp max ||k||^2
#define SMEM_BYTES 214048
#define LOD_T 32768
#define LOD_W 8192

static __device__ __forceinline__ u32 s2u(const void* p) {
    u32 a;
    asm("{ .reg .u64 t; cvta.to.shared.u64 t, %1; cvt.u32.u64 %0, t; }" : "=r"(a) : "l"(p));
    return a;
}
static __device__ __forceinline__ u32 swz(u32 o) { return o ^ ((o >> 3) & 0x70); }

static __device__ __forceinline__ void ldm4(u32* r, u32 a) {
    asm volatile("ldmatrix.sync.aligned.m8n8.x4.shared.b16 {%0,%1,%2,%3},[%4];"
                 : "=r"(r[0]), "=r"(r[1]), "=r"(r[2]), "=r"(r[3]) : "r"(a));
}
static __device__ __forceinline__ void ldm2(u32* r, u32 a) {
    asm volatile("ldmatrix.sync.aligned.m8n8.x2.shared.b16 {%0,%1},[%2];"
                 : "=r"(r[0]), "=r"(r[1]) : "r"(a));
}
static __device__ __forceinline__ void ldm2t(u32* r, u32 a) {
    asm volatile("ldmatrix.sync.aligned.m8n8.x2.trans.shared.b16 {%0,%1},[%2];"
                 : "=r"(r[0]), "=r"(r[1]) : "r"(a));
}
static __device__ __forceinline__ void hmma(float* c, const u32* a, const u32* b) {
    asm volatile("mma.sync.aligned.m16n8k16.row.col.f32.f16.f16.f32 "
                 "{%0,%1,%2,%3},{%4,%5,%6,%7},{%8,%9},{%0,%1,%2,%3};"
                 : "+f"(c[0]), "+f"(c[1]), "+f"(c[2]), "+f"(c[3])
                 : "r"(a[0]), "r"(a[1]), "r"(a[2]), "r"(a[3]), "r"(b[0]), "r"(b[1]));
}
static __device__ __forceinline__ u32 f16pk(float a, float b) {   // a -> low half
    u32 r; asm("cvt.rn.f16x2.f32 %0,%1,%2;" : "=r"(r) : "f"(b), "f"(a)); return r;
}
static __device__ __forceinline__ void h2up(u32 h, float& a, float& b) {
    asm("{.reg .b16 l,hh; mov.b32 {l,hh},%2; cvt.f32.f16 %0,l; cvt.f32.f16 %1,hh;}"
        : "=f"(a), "=f"(b) : "r"(h));
}
static __device__ __forceinline__ void split2(float a, float b, u32& hi, u32& lo) {
    u32 h = f16pk(a, b); float fa, fb; h2up(h, fa, fb);
    hi = h; lo = f16pk(a - fa, b - fb);
}
static __device__ __forceinline__ void st32(u32 a, u32 v) {
    asm volatile("st.shared.b32 [%0],%1;" :: "r"(a), "r"(v) : "memory");
}

// 64-col GEMM: c[8][4] += (Ahi+Alo)·(Bhi+Blo) 3-term split. B tiles 8(n)×4(k16).
static __device__ __forceinline__ void gemm64(float (*c)[4],
        const u32 (*ah)[4], const u32 (*al)[4],
        u32 bbase, u32 lod, int n0, int k0, int ll, bool trans) {
#pragma unroll
    for (int n = 0; n < 8; n++) {
#pragma unroll
        for (int k = 0; k < 4; k++) {
            u32 off;
            if (!trans)
                off = (u32)(n0 + 8 * n + (ll & 7)) * 128 + (u32)(k0 + 16 * k) * 2 + ((ll >> 3) & 1) * 16;
            else
                off = (u32)(k0 + 16 * k + ((ll >> 3) & 1) * 8 + (ll & 7)) * 128 + (u32)(8 * n) * 2;
            u32 a1 = bbase + swz(off);
            u32 bh[2], bl[2];
            if (trans) { ldm2t(bh, a1); ldm2t(bl, a1 + lod); }
            else       { ldm2(bh, a1);  ldm2(bl, a1 + lod); }
            hmma(c[n], ah[k], bh);
            hmma(c[n], ah[k], bl);
            hmma(c[n], al[k], bh);
        }
    }
}
// C-frag (m16 x 64) -> A-frag (m16 k64) hi/lo, register-to-register
static __device__ __forceinline__ void c2a(const float (*c)[4], u32 (*fh)[4], u32 (*fl)[4]) {
#pragma unroll
    for (int kk = 0; kk < 4; kk++) {
        split2(c[2 * kk][0],     c[2 * kk][1],     fh[kk][0], fl[kk][0]);
        split2(c[2 * kk][2],     c[2 * kk][3],     fh[kk][1], fl[kk][1]);
        split2(c[2 * kk + 1][0], c[2 * kk + 1][1], fh[kk][2], fl[kk][2]);
        split2(c[2 * kk + 1][2], c[2 * kk + 1][3], fh[kk][3], fl[kk][3]);
    }
}
static __device__ __forceinline__ void addbias(float (*c)[4], const float* __restrict__ bias, int q4) {
#pragma unroll
    for (int n = 0; n < 8; n++) {
        float b0 = bias[8 * n + 2 * q4], b1 = bias[8 * n + 2 * q4 + 1];
        c[n][0] += b0; c[n][1] += b1; c[n][2] += b0; c[n][3] += b1;
    }
}
static __device__ __forceinline__ void cstore16(const float (*c)[4], u32 base, int m0, int lane) {
    int g = lane >> 2, q4 = lane & 3;
#pragma unroll
    for (int n = 0; n < 8; n++) {
        u32 o0 = swz((u32)(m0 + g) * 128 + 16 * n + 4 * q4);
        u32 o1 = swz((u32)(m0 + g + 8) * 128 + 16 * n + 4 * q4);
        u32 h0, l0, h1, l1;
        split2(c[n][0], c[n][1], h0, l0);
        split2(c[n][2], c[n][3], h1, l1);
        st32(base + o0, h0); st32(base + LOD_T + o0, l0);
        st32(base + o1, h1); st32(base + LOD_T + o1, l1);
    }
}
static __device__ __forceinline__ void rowsum(const float (*c)[4], float& r0, float& r1) {
    float s0 = 0.f, s1 = 0.f;
#pragma unroll
    for (int n = 0; n < 8; n++) { s0 += c[n][0] + c[n][1]; s1 += c[n][2] + c[n][3]; }
    s0 += __shfl_xor_sync(~0u, s0, 1); s0 += __shfl_xor_sync(~0u, s0, 2);
    s1 += __shfl_xor_sync(~0u, s1, 1); s1 += __shfl_xor_sync(~0u, s1, 2);
    r0 = s0; r1 = s1;
}
static __device__ __forceinline__ void rowsumsq(const float (*c)[4], float& r0, float& r1) {
    float s0 = 0.f, s1 = 0.f;
#pragma unroll
    for (int n = 0; n < 8; n++) {
        s0 += c[n][0] * c[n][0] + c[n][1] * c[n][1];
        s1 += c[n][2] * c[n][2] + c[n][3] * c[n][3];
    }
    s0 += __shfl_xor_sync(~0u, s0, 1); s0 += __shfl_xor_sync(~0u, s0, 2);
    s1 += __shfl_xor_sync(~0u, s1, 1); s1 += __shfl_xor_sync(~0u, s1, 2);
    r0 = s0; r1 = s1;
}
static __device__ __forceinline__ void stageW(const float* __restrict__ W, u32 base, int tid) {
    for (int i = tid; i < 2048; i += 256) {
        int r = i >> 5, c2 = (i & 31) * 2;
        float2 w = *(const float2*)(W + r * 64 + c2);
        u32 h, l; split2(w.x, w.y, h, l);
        u32 o = swz((u32)r * 128 + (u32)c2 * 2);
        st32(base + o, h); st32(base + LOD_W + o, l);
    }
}

// ---------------- transposes ----------------
__global__ void k_tin(const float* __restrict__ in) {
    __shared__ float tile[32][33];
    int n = blockIdx.z >> 8, f = blockIdx.z & 255;
    int c0 = blockIdx.y << 5, t0 = blockIdx.x << 5;
    int tx = threadIdx.x, ty = threadIdx.y;
    int bi = ((n * 64) * 256 + f) * 256;
#pragma unroll
    for (int i = 0; i < 32; i += 8) tile[ty + i][tx] = in[bi + (c0 + ty + i) * 65536 + t0 + tx];
    __syncthreads();
    int bo = n * (256 * 16384) + f * 64;
#pragma unroll
    for (int i = 0; i < 32; i += 8) g_scratch[bo + (t0 + ty + i) * 16384 + c0 + tx] = tile[tx][ty + i];
}
__global__ void k_tout(const float* __restrict__ in, float* __restrict__ out) {
    __shared__ float tile[32][33];
    int n = blockIdx.z >> 8, f = blockIdx.z & 255;
    int c0 = blockIdx.y << 5, t0 = blockIdx.x << 5;
    int tx = threadIdx.x, ty = threadIdx.y;
    int by = n * (256 * 16384) + f * 64;
#pragma unroll
    for (int i = 0; i < 32; i += 8) tile[ty + i][tx] = g_scratch[by + (t0 + ty + i) * 16384 + c0 + tx];
    __syncthreads();
    int bo = ((n * 64) * 256 + f) * 256;
#pragma unroll
    for (int i = 0; i < 32; i += 8) {
        int a = bo + (c0 + ty + i) * 65536 + t0 + tx;
        out[a] = tile[tx][ty + i] + in[a];
    }
}

// ---------------- fused attention (mma.sync) ----------------
__global__ void __launch_bounds__(256, 1) k_attn(
    const float* __restrict__ Wq, const float* __restrict__ bq,
    const float* __restrict__ Wk, const float* __restrict__ bk,
    const float* __restrict__ Wv, const float* __restrict__ bv,
    const float* __restrict__ g1, const float* __restrict__ b1,
    const float* __restrict__ g2, const float* __restrict__ b2,
    const float* __restrict__ Wt, const float* __restrict__ bt,
    const float* __restrict__ g3, const float* __restrict__ b3,
    const float* __restrict__ alpha)
{
    extern __shared__ char smem[];
    u32 sb = s2u(smem);
    float* qn = (float*)(smem + R_QN);
    float* wkm = (float*)(smem + R_KM);
    int tid = threadIdx.x, lane = tid & 31, wrp = tid >> 5;
    int g = lane >> 2, q4 = lane & 3, ll = lane & 15;
    float* xb = g_scratch + (size_t)blockIdx.x * 16384;

    // Phase 0: LN1 (warp per row) -> H hi/lo tiles; stage Wk
    {
        float2 g1v = ((const float2*)g1)[lane];
        float2 b1v = ((const float2*)b1)[lane];
        for (int r = wrp; r < 256; r += 8) {
            float2 x = *(const float2*)(xb + r * 64 + 2 * lane);
            float s = x.x + x.y;
#pragma unroll
            for (int o = 16; o; o >>= 1) s += __shfl_xor_sync(~0u, s, o);
            float mean = s * (1.0f / 64.0f);
            float d0 = x.x - mean, d1 = x.y - mean;
            float v = d0 * d0 + d1 * d1;
#pragma unroll
            for (int o = 16; o; o >>= 1) v += __shfl_xor_sync(~0u, v, o);
            float rs = rsqrtf(v * (1.0f / 64.0f) + 1e-5f);
            u32 h, l; split2(d0 * rs * g1v.x + b1v.x, d1 * rs * g1v.y + b1v.y, h, l);
            u32 o = swz((u32)r * 128 + (u32)lane * 4);
            st32(sb + R_H + o, h); st32(sb + R_H + LOD_T + o, l);
        }
        stageW(Wk, sb + R_W, tid);
    }
    __syncthreads();

    // H A-fragments (persist through projections)
    u32 hah[2][4][4], hal[2][4][4];
#pragma unroll
    for (int mb = 0; mb < 2; mb++) {
        int m0 = wrp * 32 + mb * 16;
#pragma unroll
        for (int k = 0; k < 4; k++) {
            u32 o = swz((u32)(m0 + (lane & 15)) * 128 + (u32)k * 32 + ((lane >> 4) & 1) * 16);
            ldm4(hah[mb][k], sb + R_H + o);
            ldm4(hal[mb][k], sb + R_H + LOD_T + o);
        }
    }

    // K projection -> K tiles + max||k||^2
    {
        float kmx = 0.f;
#pragma unroll
        for (int mb = 0; mb < 2; mb++) {
            float c[8][4];
#pragma unroll
            for (int n = 0; n < 8; n++) { c[n][0] = c[n][1] = c[n][2] = c[n][3] = 0.f; }
            gemm64(c, hah[mb], hal[mb], sb + R_W, LOD_W, 0, 0, ll, false);
            addbias(c, bk, q4);
            float n0s, n1s; rowsumsq(c, n0s, n1s);
            kmx = fmaxf(kmx, fmaxf(n0s, n1s));
            cstore16(c, sb + R_K, wrp * 32 + mb * 16, lane);
        }
#pragma unroll
        for (int o = 16; o; o >>= 1) kmx = fmaxf(kmx, __shfl_xor_sync(~0u, kmx, o));
        if (lane == 0) wkm[wrp] = kmx;
    }
    __syncthreads();
    stageW(Wv, sb + R_W, tid);
    __syncthreads();

    // V projection -> V tiles
#pragma unroll
    for (int mb = 0; mb < 2; mb++) {
        float c[8][4];
#pragma unroll
        for (int n = 0; n < 8; n++) { c[n][0] = c[n][1] = c[n][2] = c[n][3] = 0.f; }
        gemm64(c, hah[mb], hal[mb], sb + R_W, LOD_W, 0, 0, ll, false);
        addbias(c, bv, q4);
        cstore16(c, sb + R_V, wrp * 32 + mb * 16, lane);
    }
    __syncthreads();
    stageW(Wq, sb + R_W, tid);
    __syncthreads();

    // Q projection -> A-fragments (registers only) + ||q||
    u32 qah[2][4][4], qal[2][4][4];
#pragma unroll
    for (int mb = 0; mb < 2; mb++) {
        int m0 = wrp * 32 + mb * 16;
        float c[8][4];
#pragma unroll
        for (int n = 0; n < 8; n++) { c[n][0] = c[n][1] = c[n][2] = c[n][3] = 0.f; }
        gemm64(c, hah[mb], hal[mb], sb + R_W, LOD_W, 0, 0, ll, false);
        addbias(c, bq, q4);
        float n0s, n1s; rowsumsq(c, n0s, n1s);
        if (q4 == 0) { qn[m0 + g] = sqrtf(n0s); qn[m0 + g + 8] = sqrtf(n1s); }
        c2a(c, qah[mb], qal[mb]);
    }
    __syncthreads();
    stageW(Wt, sb + R_W, tid);
    float kmax;
    {
        float m = wkm[0];
#pragma unroll
        for (int i = 1; i < 8; i++) m = fmaxf(m, wkm[i]);
        kmax = sqrtf(m);
    }
    __syncthreads();

    // Flash loop (sync-free): safe max = ||q||*kmax/8 - 8 (keeps p in f16-normal range)
    float mr[2][2];
#pragma unroll
    for (int mb = 0; mb < 2; mb++) {
        int m0 = wrp * 32 + mb * 16;
        mr[mb][0] = qn[m0 + g] * kmax * 0.125f - 8.0f;
        mr[mb][1] = qn[m0 + g + 8] * kmax * 0.125f - 8.0f;
    }
    float ov[2][8][4];
#pragma unroll
    for (int mb = 0; mb < 2; mb++)
#pragma unroll
        for (int n = 0; n < 8; n++) { ov[mb][n][0] = ov[mb][n][1] = ov[mb][n][2] = ov[mb][n][3] = 0.f; }

#pragma unroll 1
    for (int sc = 0; sc < 4; sc++) {
#pragma unroll
        for (int mb = 0; mb < 2; mb++) {
            float s[8][4];
#pragma unroll
            for (int n = 0; n < 8; n++) { s[n][0] = s[n][1] = s[n][2] = s[n][3] = 0.f; }
            gemm64(s, qah[mb], qal[mb], sb + R_K, LOD_T, sc * 64, 0, ll, false);
            float m0v = mr[mb][0], m1v = mr[mb][1];
#pragma unroll
            for (int n = 0; n < 8; n++) {
                s[n][0] = __expf(fmaf(s[n][0], 0.125f, -m0v));
                s[n][1] = __expf(fmaf(s[n][1], 0.125f, -m0v));
                s[n][2] = __expf(fmaf(s[n][2], 0.125f, -m1v));
                s[n][3] = __expf(fmaf(s[n][3], 0.125f, -m1v));
            }
            u32 ph[4][4], pl[4][4];
            c2a(s, ph, pl);
            gemm64(ov[mb], ph, pl, sb + R_V, LOD_T, 0, sc * 64, ll, true);
        }
    }

    // Epilogue: LN2 (regs) -> Wt GEMM -> LN3 + PReLU -> global
    float alv = __ldg(alpha);
#pragma unroll
    for (int mb = 0; mb < 2; mb++) {
        int m0 = wrp * 32 + mb * 16;
        float s0, s1, ss0, ss1;
        rowsum(ov[mb], s0, s1);
        rowsumsq(ov[mb], ss0, ss1);
        float mu0 = s0 * (1.0f / 64.0f), mu1 = s1 * (1.0f / 64.0f);
        float rs0 = rsqrtf(fmaxf(ss0 * (1.0f / 64.0f) - mu0 * mu0, 0.f) + 1e-12f);
        float rs1 = rsqrtf(fmaxf(ss1 * (1.0f / 64.0f) - mu1 * mu1, 0.f) + 1e-12f);
#pragma unroll
        for (int n = 0; n < 8; n++) {
            int c0 = 8 * n + 2 * q4;
            float2 g2v = *(const float2*)(g2 + c0);
            float2 b2v = *(const float2*)(b2 + c0);
            ov[mb][n][0] = (ov[mb][n][0] - mu0) * rs0 * g2v.x + b2v.x;
            ov[mb][n][1] = (ov[mb][n][1] - mu0) * rs0 * g2v.y + b2v.y;
            ov[mb][n][2] = (ov[mb][n][2] - mu1) * rs1 * g2v.x + b2v.x;
            ov[mb][n][3] = (ov[mb][n][3] - mu1) * rs1 * g2v.y + b2v.y;
        }
        u32 yh[4][4], yl[4][4];
        c2a(ov[mb], yh, yl);
        float y[8][4];
#pragma unroll
        for (int n = 0; n < 8; n++) { y[n][0] = y[n][1] = y[n][2] = y[n][3] = 0.f; }
        gemm64(y, yh, yl, sb + R_W, LOD_W, 0, 0, ll, false);
        addbias(y, bt, q4);
        rowsum(y, s0, s1);
        rowsumsq(y, ss0, ss1);
        mu0 = s0 * (1.0f / 64.0f); mu1 = s1 * (1.0f / 64.0f);
        rs0 = rsqrtf(ss0 * (1.0f / 64.0f) - mu0 * mu0 + 1e-5f);
        rs1 = rsqrtf(ss1 * (1.0f / 64.0f) - mu1 * mu1 + 1e-5f);
#pragma unroll
        for (int n = 0; n < 8; n++) {
            int c0 = 8 * n + 2 * q4;
            float2 g3v = *(const float2*)(g3 + c0);
            float2 b3v = *(const float2*)(b3 + c0);
            float e0 = (y[n][0] - mu0) * rs0 * g3v.x + b3v.x; e0 = e0 >= 0.f ? e0 : alv * e0;
            float e1 = (y[n][1] - mu0) * rs0 * g3v.y + b3v.y; e1 = e1 >= 0.f ? e1 : alv * e1;
            float e2 = (y[n][2] - mu1) * rs1 * g3v.x + b3v.x; e2 = e2 >= 0.f ? e2 : alv * e2;
            float e3 = (y[n][3] - mu1) * rs1 * g3v.y + b3v.y; e3 = e3 >= 0.f ? e3 : alv * e3;
            *(float2*)(xb + (m0 + g) * 64 + c0)     = make_float2(e0, e1);
            *(float2*)(xb + (m0 + g + 8) * 64 + c0) = make_float2(e2, e3);
        }
    }
}

// ---------------- launch ----------------
extern "C" void kernel_launch(void* const* d_in, const int* in_sizes, int n_in,
                              void* d_out, int out_size) {
    (void)in_sizes; (void)n_in; (void)out_size;
    const float* inputs = (const float*)d_in[0];
    const float* Wq = (const float*)d_in[1];  const float* bq = (const float*)d_in[2];
    const float* Wk = (const float*)d_in[3];  const float* bk = (const float*)d_in[4];
    const float* Wv = (const float*)d_in[5];  const float* bv = (const float*)d_in[6];
    const float* g1 = (const float*)d_in[7];  const float* b1 = (const float*)d_in[8];
    const float* g2 = (const float*)d_in[9];  const float* b2 = (const float*)d_in[10];
    const float* Wt = (const float*)d_in[11]; const float* bt = (const float*)d_in[12];
    const float* g3 = (const float*)d_in[13]; const float* b3 = (const float*)d_in[14];
    const float* alpha = (const float*)d_in[15];
    float* out = (float*)d_out;

    cudaFuncSetAttribute(k_attn, cudaFuncAttributeMaxDynamicSharedMemorySize, SMEM_BYTES);

    dim3 tgrid(8, 2, 8 * 256);
    dim3 tblk(32, 8);
    k_tin<<<tgrid, tblk>>>(inputs);
    k_attn<<<BB, 256, SMEM_BYTES>>>(Wq, bq, Wk, bk, Wv, bv, g1, b1, g2, b2,
                                    Wt, bt, g3, b3, alpha);
    k_tout<<<tgrid, tblk>>>(inputs, out);
}

// round 6
// speedup vs baseline: 2.4856x; 1.1495x over previous
#include <cuda_runtime.h>
#include <cstdint>

typedef uint32_t u32;
#define BB 2048

__device__ float g_scratch[(size_t)BB * 256 * 64];

// ---- smem regions (bytes). 256-row f16 tiles: 128B/row SW128-swizzled, hi + lo halves.
#define R_H   0          // H tile (hi), lo at +32768
#define R_K   65536
#define R_V   131072
#define R_W   196608     // 64-row weight tile (hi), lo at +8192
#define R_QN  212992     // 256 floats: ||q_row||
#define R_KM  214016     // 8 floats: per-warp max ||k||^2
#define SMEM_BYTES 214048
#define LOD_T 32768
#define LOD_W 8192

static __device__ __forceinline__ u32 s2u(const void* p) {
    u32 a;
    asm("{ .reg .u64 t; cvta.to.shared.u64 t, %1; cvt.u32.u64 %0, t; }" : "=r"(a) : "l"(p));
    return a;
}
static __device__ __forceinline__ u32 swz(u32 o) { return o ^ ((o >> 3) & 0x70); }

static __device__ __forceinline__ void ldm4(u32* r, u32 a) {
    asm volatile("ldmatrix.sync.aligned.m8n8.x4.shared.b16 {%0,%1,%2,%3},[%4];"
                 : "=r"(r[0]), "=r"(r[1]), "=r"(r[2]), "=r"(r[3]) : "r"(a));
}
static __device__ __forceinline__ void ldm2(u32* r, u32 a) {
    asm volatile("ldmatrix.sync.aligned.m8n8.x2.shared.b16 {%0,%1},[%2];"
                 : "=r"(r[0]), "=r"(r[1]) : "r"(a));
}
static __device__ __forceinline__ void ldm2t(u32* r, u32 a) {
    asm volatile("ldmatrix.sync.aligned.m8n8.x2.trans.shared.b16 {%0,%1},[%2];"
                 : "=r"(r[0]), "=r"(r[1]) : "r"(a));
}
static __device__ __forceinline__ void hmma(float* c, const u32* a, const u32* b) {
    asm volatile("mma.sync.aligned.m16n8k16.row.col.f32.f16.f16.f32 "
                 "{%0,%1,%2,%3},{%4,%5,%6,%7},{%8,%9},{%0,%1,%2,%3};"
                 : "+f"(c[0]), "+f"(c[1]), "+f"(c[2]), "+f"(c[3])
                 : "r"(a[0]), "r"(a[1]), "r"(a[2]), "r"(a[3]), "r"(b[0]), "r"(b[1]));
}
static __device__ __forceinline__ u32 f16pk(float a, float b) {   // a -> low half
    u32 r; asm("cvt.rn.f16x2.f32 %0,%1,%2;" : "=r"(r) : "f"(b), "f"(a)); return r;
}
static __device__ __forceinline__ void h2up(u32 h, float& a, float& b) {
    asm("{.reg .b16 l,hh; mov.b32 {l,hh},%2; cvt.f32.f16 %0,l; cvt.f32.f16 %1,hh;}"
        : "=f"(a), "=f"(b) : "r"(h));
}
static __device__ __forceinline__ void split2(float a, float b, u32& hi, u32& lo) {
    u32 h = f16pk(a, b); float fa, fb; h2up(h, fa, fb);
    hi = h; lo = f16pk(a - fa, b - fb);
}
static __device__ __forceinline__ void st32(u32 a, u32 v) {
    asm volatile("st.shared.b32 [%0],%1;" :: "r"(a), "r"(v) : "memory");
}

// Dual-A 64-col GEMM, 3-term hi/lo split. B fragments loaded ONCE per n-slice
// (batched 8 LDSM, then 24 HMMAs over two independent accumulator sets).
static __device__ __forceinline__ void gemm64d(float (*c0)[4], float (*c1)[4],
        const u32 (*a0h)[4], const u32 (*a0l)[4],
        const u32 (*a1h)[4], const u32 (*a1l)[4],
        u32 bbase, u32 lod, int n0, int k0, int ll, bool trans) {
#pragma unroll
    for (int n = 0; n < 8; n++) {
        u32 bh[4][2], bl[4][2];
#pragma unroll
        for (int k = 0; k < 4; k++) {
            u32 off;
            if (!trans)
                off = (u32)(n0 + 8 * n + (ll & 7)) * 128 + (u32)(k0 + 16 * k) * 2 + ((ll >> 3) & 1) * 16;
            else
                off = (u32)(k0 + 16 * k + ((ll >> 3) & 1) * 8 + (ll & 7)) * 128 + (u32)(8 * n) * 2;
            u32 a = bbase + swz(off);
            if (trans) { ldm2t(bh[k], a); ldm2t(bl[k], a + lod); }
            else       { ldm2(bh[k], a);  ldm2(bl[k], a + lod); }
        }
#pragma unroll
        for (int k = 0; k < 4; k++) {
            hmma(c0[n], a0h[k], bh[k]); hmma(c1[n], a1h[k], bh[k]);
            hmma(c0[n], a0h[k], bl[k]); hmma(c1[n], a1h[k], bl[k]);
            hmma(c0[n], a0l[k], bh[k]); hmma(c1[n], a1l[k], bh[k]);
        }
    }
}
// C-frag (m16 x 64) -> A-frag (m16 k64) hi/lo, register-to-register
static __device__ __forceinline__ void c2a(const float (*c)[4], u32 (*fh)[4], u32 (*fl)[4]) {
#pragma unroll
    for (int kk = 0; kk < 4; kk++) {
        split2(c[2 * kk][0],     c[2 * kk][1],     fh[kk][0], fl[kk][0]);
        split2(c[2 * kk][2],     c[2 * kk][3],     fh[kk][1], fl[kk][1]);
        split2(c[2 * kk + 1][0], c[2 * kk + 1][1], fh[kk][2], fl[kk][2]);
        split2(c[2 * kk + 1][2], c[2 * kk + 1][3], fh[kk][3], fl[kk][3]);
    }
}
static __device__ __forceinline__ void addbias(float (*c)[4], const float* __restrict__ bias, int q4) {
#pragma unroll
    for (int n = 0; n < 8; n++) {
        float b0 = bias[8 * n + 2 * q4], b1 = bias[8 * n + 2 * q4 + 1];
        c[n][0] += b0; c[n][1] += b1; c[n][2] += b0; c[n][3] += b1;
    }
}
static __device__ __forceinline__ void cstore16(const float (*c)[4], u32 base, int m0, int lane) {
    int g = lane >> 2, q4 = lane & 3;
#pragma unroll
    for (int n = 0; n < 8; n++) {
        u32 o0 = swz((u32)(m0 + g) * 128 + 16 * n + 4 * q4);
        u32 o1 = swz((u32)(m0 + g + 8) * 128 + 16 * n + 4 * q4);
        u32 h0, l0, h1, l1;
        split2(c[n][0], c[n][1], h0, l0);
        split2(c[n][2], c[n][3], h1, l1);
        st32(base + o0, h0); st32(base + LOD_T + o0, l0);
        st32(base + o1, h1); st32(base + LOD_T + o1, l1);
    }
}
static __device__ __forceinline__ void rowsum(const float (*c)[4], float& r0, float& r1) {
    float s0 = 0.f, s1 = 0.f;
#pragma unroll
    for (int n = 0; n < 8; n++) { s0 += c[n][0] + c[n][1]; s1 += c[n][2] + c[n][3]; }
    s0 += __shfl_xor_sync(~0u, s0, 1); s0 += __shfl_xor_sync(~0u, s0, 2);
    s1 += __shfl_xor_sync(~0u, s1, 1); s1 += __shfl_xor_sync(~0u, s1, 2);
    r0 = s0; r1 = s1;
}
static __device__ __forceinline__ void rowsumsq(const float (*c)[4], float& r0, float& r1) {
    float s0 = 0.f, s1 = 0.f;
#pragma unroll
    for (int n = 0; n < 8; n++) {
        s0 += c[n][0] * c[n][0] + c[n][1] * c[n][1];
        s1 += c[n][2] * c[n][2] + c[n][3] * c[n][3];
    }
    s0 += __shfl_xor_sync(~0u, s0, 1); s0 += __shfl_xor_sync(~0u, s0, 2);
    s1 += __shfl_xor_sync(~0u, s1, 1); s1 += __shfl_xor_sync(~0u, s1, 2);
    r0 = s0; r1 = s1;
}
static __device__ __forceinline__ void stageW(const float* __restrict__ W, u32 base, int tid) {
    for (int i = tid; i < 2048; i += 256) {
        int r = i >> 5, c2 = (i & 31) * 2;
        float2 w = *(const float2*)(W + r * 64 + c2);
        u32 h, l; split2(w.x, w.y, h, l);
        u32 o = swz((u32)r * 128 + (u32)c2 * 2);
        st32(base + o, h); st32(base + LOD_W + o, l);
    }
}

// ---------------- transposes ----------------
__global__ void k_tin(const float* __restrict__ in) {
    __shared__ float tile[32][33];
    int n = blockIdx.z >> 8, f = blockIdx.z & 255;
    int c0 = blockIdx.y << 5, t0 = blockIdx.x << 5;
    int tx = threadIdx.x, ty = threadIdx.y;
    int bi = ((n * 64) * 256 + f) * 256;
#pragma unroll
    for (int i = 0; i < 32; i += 8) tile[ty + i][tx] = in[bi + (c0 + ty + i) * 65536 + t0 + tx];
    __syncthreads();
    int bo = n * (256 * 16384) + f * 64;
#pragma unroll
    for (int i = 0; i < 32; i += 8) g_scratch[bo + (t0 + ty + i) * 16384 + c0 + tx] = tile[tx][ty + i];
}
__global__ void k_tout(const float* __restrict__ in, float* __restrict__ out) {
    __shared__ float tile[32][33];
    int n = blockIdx.z >> 8, f = blockIdx.z & 255;
    int c0 = blockIdx.y << 5, t0 = blockIdx.x << 5;
    int tx = threadIdx.x, ty = threadIdx.y;
    int by = n * (256 * 16384) + f * 64;
#pragma unroll
    for (int i = 0; i < 32; i += 8) tile[ty + i][tx] = g_scratch[by + (t0 + ty + i) * 16384 + c0 + tx];
    __syncthreads();
    int bo = ((n * 64) * 256 + f) * 256;
#pragma unroll
    for (int i = 0; i < 32; i += 8) {
        int a = bo + (c0 + ty + i) * 65536 + t0 + tx;
        out[a] = tile[tx][ty + i] + in[a];
    }
}

// ---------------- fused attention (mma.sync, dual-A) ----------------
__global__ void __launch_bounds__(256, 1) k_attn(
    const float* __restrict__ Wq, const float* __restrict__ bq,
    const float* __restrict__ Wk, const float* __restrict__ bk,
    const float* __restrict__ Wv, const float* __restrict__ bv,
    const float* __restrict__ g1, const float* __restrict__ b1,
    const float* __restrict__ g2, const float* __restrict__ b2,
    const float* __restrict__ Wt, const float* __restrict__ bt,
    const float* __restrict__ g3, const float* __restrict__ b3,
    const float* __restrict__ alpha)
{
    extern __shared__ char smem[];
    u32 sb = s2u(smem);
    float* qn = (float*)(smem + R_QN);
    float* wkm = (float*)(smem + R_KM);
    int tid = threadIdx.x, lane = tid & 31, wrp = tid >> 5;
    int g = lane >> 2, q4 = lane & 3, ll = lane & 15;
    float* xb = g_scratch + (size_t)blockIdx.x * 16384;

    // Phase 0: LN1 (warp per row) -> H hi/lo tiles; stage Wk
    {
        float2 g1v = ((const float2*)g1)[lane];
        float2 b1v = ((const float2*)b1)[lane];
        for (int r = wrp; r < 256; r += 8) {
            float2 x = *(const float2*)(xb + r * 64 + 2 * lane);
            float s = x.x + x.y;
#pragma unroll
            for (int o = 16; o; o >>= 1) s += __shfl_xor_sync(~0u, s, o);
            float mean = s * (1.0f / 64.0f);
            float d0 = x.x - mean, d1 = x.y - mean;
            float v = d0 * d0 + d1 * d1;
#pragma unroll
            for (int o = 16; o; o >>= 1) v += __shfl_xor_sync(~0u, v, o);
            float rs = rsqrtf(v * (1.0f / 64.0f) + 1e-5f);
            u32 h, l; split2(d0 * rs * g1v.x + b1v.x, d1 * rs * g1v.y + b1v.y, h, l);
            u32 o = swz((u32)r * 128 + (u32)lane * 4);
            st32(sb + R_H + o, h); st32(sb + R_H + LOD_T + o, l);
        }
        stageW(Wk, sb + R_W, tid);
    }
    __syncthreads();

    // H A-fragments (persist through projections)
    u32 hah[2][4][4], hal[2][4][4];
#pragma unroll
    for (int mb = 0; mb < 2; mb++) {
        int m0 = wrp * 32 + mb * 16;
#pragma unroll
        for (int k = 0; k < 4; k++) {
            u32 o = swz((u32)(m0 + (lane & 15)) * 128 + (u32)k * 32 + ((lane >> 4) & 1) * 16);
            ldm4(hah[mb][k], sb + R_H + o);
            ldm4(hal[mb][k], sb + R_H + LOD_T + o);
        }
    }

    // K projection -> K tiles + max||k||^2
    {
        float c0[8][4], c1[8][4];
#pragma unroll
        for (int n = 0; n < 8; n++) {
            c0[n][0] = c0[n][1] = c0[n][2] = c0[n][3] = 0.f;
            c1[n][0] = c1[n][1] = c1[n][2] = c1[n][3] = 0.f;
        }
        gemm64d(c0, c1, hah[0], hal[0], hah[1], hal[1], sb + R_W, LOD_W, 0, 0, ll, false);
        addbias(c0, bk, q4); addbias(c1, bk, q4);
        float a0, a1, a2, a3;
        rowsumsq(c0, a0, a1); rowsumsq(c1, a2, a3);
        float kmx = fmaxf(fmaxf(a0, a1), fmaxf(a2, a3));
#pragma unroll
        for (int o = 16; o; o >>= 1) kmx = fmaxf(kmx, __shfl_xor_sync(~0u, kmx, o));
        if (lane == 0) wkm[wrp] = kmx;
        cstore16(c0, sb + R_K, wrp * 32, lane);
        cstore16(c1, sb + R_K, wrp * 32 + 16, lane);
    }
    __syncthreads();
    stageW(Wv, sb + R_W, tid);
    __syncthreads();

    // V projection -> V tiles
    {
        float c0[8][4], c1[8][4];
#pragma unroll
        for (int n = 0; n < 8; n++) {
            c0[n][0] = c0[n][1] = c0[n][2] = c0[n][3] = 0.f;
            c1[n][0] = c1[n][1] = c1[n][2] = c1[n][3] = 0.f;
        }
        gemm64d(c0, c1, hah[0], hal[0], hah[1], hal[1], sb + R_W, LOD_W, 0, 0, ll, false);
        addbias(c0, bv, q4); addbias(c1, bv, q4);
        cstore16(c0, sb + R_V, wrp * 32, lane);
        cstore16(c1, sb + R_V, wrp * 32 + 16, lane);
    }
    __syncthreads();
    stageW(Wq, sb + R_W, tid);
    __syncthreads();

    // Q projection -> A-fragments (registers only) + ||q||
    u32 qah[2][4][4], qal[2][4][4];
    {
        float c0[8][4], c1[8][4];
#pragma unroll
        for (int n = 0; n < 8; n++) {
            c0[n][0] = c0[n][1] = c0[n][2] = c0[n][3] = 0.f;
            c1[n][0] = c1[n][1] = c1[n][2] = c1[n][3] = 0.f;
        }
        gemm64d(c0, c1, hah[0], hal[0], hah[1], hal[1], sb + R_W, LOD_W, 0, 0, ll, false);
        addbias(c0, bq, q4); addbias(c1, bq, q4);
        float a0, a1, a2, a3;
        rowsumsq(c0, a0, a1); rowsumsq(c1, a2, a3);
        if (q4 == 0) {
            int m0 = wrp * 32;
            qn[m0 + g] = sqrtf(a0); qn[m0 + g + 8] = sqrtf(a1);
            qn[m0 + 16 + g] = sqrtf(a2); qn[m0 + 24 + g] = sqrtf(a3);
        }
        c2a(c0, qah[0], qal[0]);
        c2a(c1, qah[1], qal[1]);
    }
    __syncthreads();
    stageW(Wt, sb + R_W, tid);
    float kmax;
    {
        float m = wkm[0];
#pragma unroll
        for (int i = 1; i < 8; i++) m = fmaxf(m, wkm[i]);
        kmax = sqrtf(m);
    }
    __syncthreads();

    // Flash loop (sync-free): safe max = ||q||*kmax/8 - 8 (keeps p in f16-normal range)
    float mr[2][2];
#pragma unroll
    for (int mb = 0; mb < 2; mb++) {
        int m0 = wrp * 32 + mb * 16;
        mr[mb][0] = qn[m0 + g] * kmax * 0.125f - 8.0f;
        mr[mb][1] = qn[m0 + g + 8] * kmax * 0.125f - 8.0f;
    }
    float ov[2][8][4];
#pragma unroll
    for (int mb = 0; mb < 2; mb++)
#pragma unroll
        for (int n = 0; n < 8; n++) { ov[mb][n][0] = ov[mb][n][1] = ov[mb][n][2] = ov[mb][n][3] = 0.f; }

#pragma unroll 1
    for (int sc = 0; sc < 4; sc++) {
        float s0[8][4], s1[8][4];
#pragma unroll
        for (int n = 0; n < 8; n++) {
            s0[n][0] = s0[n][1] = s0[n][2] = s0[n][3] = 0.f;
            s1[n][0] = s1[n][1] = s1[n][2] = s1[n][3] = 0.f;
        }
        gemm64d(s0, s1, qah[0], qal[0], qah[1], qal[1], sb + R_K, LOD_T, sc * 64, 0, ll, false);
#pragma unroll
        for (int n = 0; n < 8; n++) {
            s0[n][0] = __expf(fmaf(s0[n][0], 0.125f, -mr[0][0]));
            s0[n][1] = __expf(fmaf(s0[n][1], 0.125f, -mr[0][0]));
            s0[n][2] = __expf(fmaf(s0[n][2], 0.125f, -mr[0][1]));
            s0[n][3] = __expf(fmaf(s0[n][3], 0.125f, -mr[0][1]));
            s1[n][0] = __expf(fmaf(s1[n][0], 0.125f, -mr[1][0]));
            s1[n][1] = __expf(fmaf(s1[n][1], 0.125f, -mr[1][0]));
            s1[n][2] = __expf(fmaf(s1[n][2], 0.125f, -mr[1][1]));
            s1[n][3] = __expf(fmaf(s1[n][3], 0.125f, -mr[1][1]));
        }
        u32 p0h[4][4], p0l[4][4], p1h[4][4], p1l[4][4];
        c2a(s0, p0h, p0l); c2a(s1, p1h, p1l);
        gemm64d(ov[0], ov[1], p0h, p0l, p1h, p1l, sb + R_V, LOD_T, 0, sc * 64, ll, true);
    }

    // Epilogue: LN2 (regs) -> Wt GEMM -> LN3 + PReLU -> global
    float alv = __ldg(alpha);
#pragma unroll
    for (int mb = 0; mb < 2; mb++) {
        float s0v, s1v, ss0, ss1;
        rowsum(ov[mb], s0v, s1v);
        rowsumsq(ov[mb], ss0, ss1);
        float mu0 = s0v * (1.0f / 64.0f), mu1 = s1v * (1.0f / 64.0f);
        float rs0 = rsqrtf(fmaxf(ss0 * (1.0f / 64.0f) - mu0 * mu0, 0.f) + 1e-12f);
        float rs1 = rsqrtf(fmaxf(ss1 * (1.0f / 64.0f) - mu1 * mu1, 0.f) + 1e-12f);
#pragma unroll
        for (int n = 0; n < 8; n++) {
            int c0i = 8 * n + 2 * q4;
            float2 g2v = *(const float2*)(g2 + c0i);
            float2 b2v = *(const float2*)(b2 + c0i);
            ov[mb][n][0] = (ov[mb][n][0] - mu0) * rs0 * g2v.x + b2v.x;
            ov[mb][n][1] = (ov[mb][n][1] - mu0) * rs0 * g2v.y + b2v.y;
            ov[mb][n][2] = (ov[mb][n][2] - mu1) * rs1 * g2v.x + b2v.x;
            ov[mb][n][3] = (ov[mb][n][3] - mu1) * rs1 * g2v.y + b2v.y;
        }
    }
    u32 yh0[4][4], yl0[4][4], yh1[4][4], yl1[4][4];
    c2a(ov[0], yh0, yl0);
    c2a(ov[1], yh1, yl1);
    float y[2][8][4];
#pragma unroll
    for (int mb = 0; mb < 2; mb++)
#pragma unroll
        for (int n = 0; n < 8; n++) { y[mb][n][0] = y[mb][n][1] = y[mb][n][2] = y[mb][n][3] = 0.f; }
    gemm64d(y[0], y[1], yh0, yl0, yh1, yl1, sb + R_W, LOD_W, 0, 0, ll, false);
#pragma unroll
    for (int mb = 0; mb < 2; mb++) {
        int m0 = wrp * 32 + mb * 16;
        addbias(y[mb], bt, q4);
        float s0v, s1v, ss0, ss1;
        rowsum(y[mb], s0v, s1v);
        rowsumsq(y[mb], ss0, ss1);
        float mu0 = s0v * (1.0f / 64.0f), mu1 = s1v * (1.0f / 64.0f);
        float rs0 = rsqrtf(ss0 * (1.0f / 64.0f) - mu0 * mu0 + 1e-5f);
        float rs1 = rsqrtf(ss1 * (1.0f / 64.0f) - mu1 * mu1 + 1e-5f);
#pragma unroll
        for (int n = 0; n < 8; n++) {
            int c0i = 8 * n + 2 * q4;
            float2 g3v = *(const float2*)(g3 + c0i);
            float2 b3v = *(const float2*)(b3 + c0i);
            float e0 = (y[mb][n][0] - mu0) * rs0 * g3v.x + b3v.x; e0 = e0 >= 0.f ? e0 : alv * e0;
            float e1 = (y[mb][n][1] - mu0) * rs0 * g3v.y + b3v.y; e1 = e1 >= 0.f ? e1 : alv * e1;
            float e2 = (y[mb][n][2] - mu1) * rs1 * g3v.x + b3v.x; e2 = e2 >= 0.f ? e2 : alv * e2;
            float e3 = (y[mb][n][3] - mu1) * rs1 * g3v.y + b3v.y; e3 = e3 >= 0.f ? e3 : alv * e3;
            *(float2*)(xb + (m0 + g) * 64 + c0i)     = make_float2(e0, e1);
            *(float2*)(xb + (m0 + g + 8) * 64 + c0i) = make_float2(e2, e3);
        }
    }
}

// ---------------- launch ----------------
extern "C" void kernel_launch(void* const* d_in, const int* in_sizes, int n_in,
                              void* d_out, int out_size) {
    (void)in_sizes; (void)n_in; (void)out_size;
    const float* inputs = (const float*)d_in[0];
    const float* Wq = (const float*)d_in[1];  const float* bq = (const float*)d_in[2];
    const float* Wk = (const float*)d_in[3];  const float* bk = (const float*)d_in[4];
    const float* Wv = (const float*)d_in[5];  const float* bv = (const float*)d_in[6];
    const float* g1 = (const float*)d_in[7];  const float* b1 = (const float*)d_in[8];
    const float* g2 = (const float*)d_in[9];  const float* b2 = (const float*)d_in[10];
    const float* Wt = (const float*)d_in[11]; const float* bt = (const float*)d_in[12];
    const float* g3 = (const float*)d_in[13]; const float* b3 = (const float*)d_in[14];
    const float* alpha = (const float*)d_in[15];
    float* out = (float*)d_out;

    cudaFuncSetAttribute(k_attn, cudaFuncAttributeMaxDynamicSharedMemorySize, SMEM_BYTES);

    dim3 tgrid(8, 2, 8 * 256);
    dim3 tblk(32, 8);
    k_tin<<<tgrid, tblk>>>(inputs);
    k_attn<<<BB, 256, SMEM_BYTES>>>(Wq, bq, Wk, bk, Wv, bv, g1, b1, g2, b2,
                                    Wt, bt, g3, b3, alpha);
    k_tout<<<tgrid, tblk>>>(inputs, out);
}

// round 8
// speedup vs baseline: 2.8846x; 1.1605x over previous
#include <cuda_runtime.h>
#include <cstdint>

typedef uint32_t u32;
#define BB 2048

__device__ float g_scratch[(size_t)BB * 256 * 64];

// ---- smem map (bytes) ----
// Phase 1: R_H = H tile (hi @0, lo @32768), 64KB
// Phase 2+ (H dead): weights Wk@0/8192, Wv@16384/24576, Wq@32768/40960, Wt@49152/57344
#define R_H   0
#define R_WK  0
#define R_WV  16384
#define R_WQ  32768
#define R_WT  49152
#define R_K   65536      // K tiles hi/lo (64KB)
#define R_V   131072     // V tiles hi/lo (64KB)
#define R_KM  196608     // 16 floats: per-warp max ||k||^2
#define SMEM_BYTES 196672
#define LOD_T 32768
#define LOD_W 8192

static __device__ __forceinline__ u32 s2u(const void* p) {
    u32 a;
    asm("{ .reg .u64 t; cvta.to.shared.u64 t, %1; cvt.u32.u64 %0, t; }" : "=r"(a) : "l"(p));
    return a;
}
static __device__ __forceinline__ u32 swz(u32 o) { return o ^ ((o >> 3) & 0x70); }

static __device__ __forceinline__ void ldm4(u32* r, u32 a) {
    asm volatile("ldmatrix.sync.aligned.m8n8.x4.shared.b16 {%0,%1,%2,%3},[%4];"
                 : "=r"(r[0]), "=r"(r[1]), "=r"(r[2]), "=r"(r[3]) : "r"(a));
}
static __device__ __forceinline__ void ldm2(u32* r, u32 a) {
    asm volatile("ldmatrix.sync.aligned.m8n8.x2.shared.b16 {%0,%1},[%2];"
                 : "=r"(r[0]), "=r"(r[1]) : "r"(a));
}
static __device__ __forceinline__ void ldm2t(u32* r, u32 a) {
    asm volatile("ldmatrix.sync.aligned.m8n8.x2.trans.shared.b16 {%0,%1},[%2];"
                 : "=r"(r[0]), "=r"(r[1]) : "r"(a));
}
static __device__ __forceinline__ void hmma(float* c, const u32* a, const u32* b) {
    asm volatile("mma.sync.aligned.m16n8k16.row.col.f32.f16.f16.f32 "
                 "{%0,%1,%2,%3},{%4,%5,%6,%7},{%8,%9},{%0,%1,%2,%3};"
                 : "+f"(c[0]), "+f"(c[1]), "+f"(c[2]), "+f"(c[3])
                 : "r"(a[0]), "r"(a[1]), "r"(a[2]), "r"(a[3]), "r"(b[0]), "r"(b[1]));
}
static __device__ __forceinline__ u32 f16pk(float a, float b) {   // a -> low half
    u32 r; asm("cvt.rn.f16x2.f32 %0,%1,%2;" : "=r"(r) : "f"(b), "f"(a)); return r;
}
static __device__ __forceinline__ void h2up(u32 h, float& a, float& b) {
    asm("{.reg .b16 l,hh; mov.b32 {l,hh},%2; cvt.f32.f16 %0,l; cvt.f32.f16 %1,hh;}"
        : "=f"(a), "=f"(b) : "r"(h));
}
static __device__ __forceinline__ void split2(float a, float b, u32& hi, u32& lo) {
    u32 h = f16pk(a, b); float fa, fb; h2up(h, fa, fb);
    hi = h; lo = f16pk(a - fa, b - fb);
}
static __device__ __forceinline__ void st32(u32 a, u32 v) {
    asm volatile("st.shared.b32 [%0],%1;" :: "r"(a), "r"(v) : "memory");
}

// 64-col GEMM, 3-term hi/lo split, paired-n interleave (2 independent acc chains,
// B fragments shared per pair, batched LDSM before the 6 HMMAs).
static __device__ __forceinline__ void gemm64(float (*c)[4],
        const u32 (*ah)[4], const u32 (*al)[4],
        u32 bbase, u32 lod, int n0, int k0, int ll, bool trans) {
#pragma unroll
    for (int np = 0; np < 4; np++) {
#pragma unroll
        for (int k = 0; k < 4; k++) {
            u32 offA, offB;
            if (!trans) {
                offA = (u32)(n0 + 16 * np + (ll & 7)) * 128 + (u32)(k0 + 16 * k) * 2 + ((ll >> 3) & 1) * 16;
                offB = offA + 8 * 128;
            } else {
                offA = (u32)(k0 + 16 * k + ((ll >> 3) & 1) * 8 + (ll & 7)) * 128 + (u32)(32 * np);
                offB = offA + 16;
            }
            u32 aA = bbase + swz(offA), aB = bbase + swz(offB);
            u32 bhA[2], blA[2], bhB[2], blB[2];
            if (trans) { ldm2t(bhA, aA); ldm2t(bhB, aB); ldm2t(blA, aA + lod); ldm2t(blB, aB + lod); }
            else       { ldm2(bhA, aA);  ldm2(bhB, aB);  ldm2(blA, aA + lod);  ldm2(blB, aB + lod); }
            hmma(c[2 * np], ah[k], bhA); hmma(c[2 * np + 1], ah[k], bhB);
            hmma(c[2 * np], ah[k], blA); hmma(c[2 * np + 1], ah[k], blB);
            hmma(c[2 * np], al[k], bhA); hmma(c[2 * np + 1], al[k], bhB);
        }
    }
}
// C-frag (m16 x 64) -> A-frag (m16 k64) hi/lo, register-to-register
static __device__ __forceinline__ void c2a(const float (*c)[4], u32 (*fh)[4], u32 (*fl)[4]) {
#pragma unroll
    for (int kk = 0; kk < 4; kk++) {
        split2(c[2 * kk][0],     c[2 * kk][1],     fh[kk][0], fl[kk][0]);
        split2(c[2 * kk][2],     c[2 * kk][3],     fh[kk][1], fl[kk][1]);
        split2(c[2 * kk + 1][0], c[2 * kk + 1][1], fh[kk][2], fl[kk][2]);
        split2(c[2 * kk + 1][2], c[2 * kk + 1][3], fh[kk][3], fl[kk][3]);
    }
}
static __device__ __forceinline__ void addbias(float (*c)[4], const float* __restrict__ bias, int q4) {
#pragma unroll
    for (int n = 0; n < 8; n++) {
        float b0 = bias[8 * n + 2 * q4], b1 = bias[8 * n + 2 * q4 + 1];
        c[n][0] += b0; c[n][1] += b1; c[n][2] += b0; c[n][3] += b1;
    }
}
static __device__ __forceinline__ void cstore16(const float (*c)[4], u32 base, int m0, int lane) {
    int g = lane >> 2, q4 = lane & 3;
#pragma unroll
    for (int n = 0; n < 8; n++) {
        u32 o0 = swz((u32)(m0 + g) * 128 + 16 * n + 4 * q4);
        u32 o1 = swz((u32)(m0 + g + 8) * 128 + 16 * n + 4 * q4);
        u32 h0, l0, h1, l1;
        split2(c[n][0], c[n][1], h0, l0);
        split2(c[n][2], c[n][3], h1, l1);
        st32(base + o0, h0); st32(base + LOD_T + o0, l0);
        st32(base + o1, h1); st32(base + LOD_T + o1, l1);
    }
}
static __device__ __forceinline__ void rowsum(const float (*c)[4], float& r0, float& r1) {
    float s0 = 0.f, s1 = 0.f;
#pragma unroll
    for (int n = 0; n < 8; n++) { s0 += c[n][0] + c[n][1]; s1 += c[n][2] + c[n][3]; }
    s0 += __shfl_xor_sync(~0u, s0, 1); s0 += __shfl_xor_sync(~0u, s0, 2);
    s1 += __shfl_xor_sync(~0u, s1, 1); s1 += __shfl_xor_sync(~0u, s1, 2);
    r0 = s0; r1 = s1;
}
static __device__ __forceinline__ void rowsumsq(const float (*c)[4], float& r0, float& r1) {
    float s0 = 0.f, s1 = 0.f;
#pragma unroll
    for (int n = 0; n < 8; n++) {
        s0 += c[n][0] * c[n][0] + c[n][1] * c[n][1];
        s1 += c[n][2] * c[n][2] + c[n][3] * c[n][3];
    }
    s0 += __shfl_xor_sync(~0u, s0, 1); s0 += __shfl_xor_sync(~0u, s0, 2);
    s1 += __shfl_xor_sync(~0u, s1, 1); s1 += __shfl_xor_sync(~0u, s1, 2);
    r0 = s0; r1 = s1;
}
static __device__ __forceinline__ void stageW(const float* __restrict__ W, u32 base, int tid) {
    for (int i = tid; i < 2048; i += 512) {
        int r = i >> 5, c2 = (i & 31) * 2;
        float2 w = *(const float2*)(W + r * 64 + c2);
        u32 h, l; split2(w.x, w.y, h, l);
        u32 o = swz((u32)r * 128 + (u32)c2 * 2);
        st32(base + o, h); st32(base + LOD_W + o, l);
    }
}

// ---------------- transposes ----------------
__global__ void k_tin(const float* __restrict__ in) {
    __shared__ float tile[32][33];
    int n = blockIdx.z >> 8, f = blockIdx.z & 255;
    int c0 = blockIdx.y << 5, t0 = blockIdx.x << 5;
    int tx = threadIdx.x, ty = threadIdx.y;
    int bi = ((n * 64) * 256 + f) * 256;
#pragma unroll
    for (int i = 0; i < 32; i += 8) tile[ty + i][tx] = in[bi + (c0 + ty + i) * 65536 + t0 + tx];
    __syncthreads();
    int bo = n * (256 * 16384) + f * 64;
#pragma unroll
    for (int i = 0; i < 32; i += 8) g_scratch[bo + (t0 + ty + i) * 16384 + c0 + tx] = tile[tx][ty + i];
}
__global__ void k_tout(const float* __restrict__ in, float* __restrict__ out) {
    __shared__ float tile[32][33];
    int n = blockIdx.z >> 8, f = blockIdx.z & 255;
    int c0 = blockIdx.y << 5, t0 = blockIdx.x << 5;
    int tx = threadIdx.x, ty = threadIdx.y;
    int by = n * (256 * 16384) + f * 64;
#pragma unroll
    for (int i = 0; i < 32; i += 8) tile[ty + i][tx] = g_scratch[by + (t0 + ty + i) * 16384 + c0 + tx];
    __syncthreads();
    int bo = ((n * 64) * 256 + f) * 256;
#pragma unroll
    for (int i = 0; i < 32; i += 8) {
        int a = bo + (c0 + ty + i) * 65536 + t0 + tx;
        out[a] = tile[tx][ty + i] + in[a];
    }
}

// ---------------- fused attention (mma.sync, 512 threads, 16 rows/warp) ----------------
__global__ void __launch_bounds__(512, 1) k_attn(
    const float* __restrict__ Wq, const float* __restrict__ bq,
    const float* __restrict__ Wk, const float* __restrict__ bk,
    const float* __restrict__ Wv, const float* __restrict__ bv,
    const float* __restrict__ g1, const float* __restrict__ b1,
    const float* __restrict__ g2, const float* __restrict__ b2,
    const float* __restrict__ Wt, const float* __restrict__ bt,
    const float* __restrict__ g3, const float* __restrict__ b3,
    const float* __restrict__ alpha)
{
    extern __shared__ char smem[];
    u32 sb = s2u(smem);
    float* wkm = (float*)(smem + R_KM);
    int tid = threadIdx.x, lane = tid & 31, wrp = tid >> 5;
    int g = lane >> 2, q4 = lane & 3, ll = lane & 15;
    int m0 = wrp * 16;
    float* xb = g_scratch + (size_t)blockIdx.x * 16384;

    // Phase 0: LN1 (warp per row, 16 warps) -> H hi/lo tiles
    {
        float2 g1v = ((const float2*)g1)[lane];
        float2 b1v = ((const float2*)b1)[lane];
        for (int r = wrp; r < 256; r += 16) {
            float2 x = *(const float2*)(xb + r * 64 + 2 * lane);
            float s = x.x + x.y;
#pragma unroll
            for (int o = 16; o; o >>= 1) s += __shfl_xor_sync(~0u, s, o);
            float mean = s * (1.0f / 64.0f);
            float d0 = x.x - mean, d1 = x.y - mean;
            float v = d0 * d0 + d1 * d1;
#pragma unroll
            for (int o = 16; o; o >>= 1) v += __shfl_xor_sync(~0u, v, o);
            float rs = rsqrtf(v * (1.0f / 64.0f) + 1e-5f);
            u32 h, l; split2(d0 * rs * g1v.x + b1v.x, d1 * rs * g1v.y + b1v.y, h, l);
            u32 o = swz((u32)r * 128 + (u32)lane * 4);
            st32(sb + R_H + o, h); st32(sb + R_H + LOD_T + o, l);
        }
    }
    __syncthreads();

    // H A-fragments for this warp's 16 rows
    u32 hah[4][4], hal[4][4];
#pragma unroll
    for (int k = 0; k < 4; k++) {
        u32 o = swz((u32)(m0 + (lane & 15)) * 128 + (u32)k * 32 + ((lane >> 4) & 1) * 16);
        ldm4(hah[k], sb + R_H + o);
        ldm4(hal[k], sb + R_H + LOD_T + o);
    }
    __syncthreads();   // H tiles fully consumed -> region becomes weight storage

    stageW(Wk, sb + R_WK, tid);
    stageW(Wv, sb + R_WV, tid);
    stageW(Wq, sb + R_WQ, tid);
    stageW(Wt, sb + R_WT, tid);
    __syncthreads();

    // K projection -> K tiles + max||k||^2
    {
        float c[8][4];
#pragma unroll
        for (int n = 0; n < 8; n++) { c[n][0] = c[n][1] = c[n][2] = c[n][3] = 0.f; }
        gemm64(c, hah, hal, sb + R_WK, LOD_W, 0, 0, ll, false);
        addbias(c, bk, q4);
        float a0, a1; rowsumsq(c, a0, a1);
        float kmx = fmaxf(a0, a1);
#pragma unroll
        for (int o = 16; o; o >>= 1) kmx = fmaxf(kmx, __shfl_xor_sync(~0u, kmx, o));
        if (lane == 0) wkm[wrp] = kmx;
        cstore16(c, sb + R_K, m0, lane);
    }
    // V projection -> V tiles
    {
        float c[8][4];
#pragma unroll
        for (int n = 0; n < 8; n++) { c[n][0] = c[n][1] = c[n][2] = c[n][3] = 0.f; }
        gemm64(c, hah, hal, sb + R_WV, LOD_W, 0, 0, ll, false);
        addbias(c, bv, q4);
        cstore16(c, sb + R_V, m0, lane);
    }
    // Q projection -> A-fragments (registers only) + ||q|| (regs)
    u32 qah[4][4], qal[4][4];
    float qn0, qn1;
    {
        float c[8][4];
#pragma unroll
        for (int n = 0; n < 8; n++) { c[n][0] = c[n][1] = c[n][2] = c[n][3] = 0.f; }
        gemm64(c, hah, hal, sb + R_WQ, LOD_W, 0, 0, ll, false);
        addbias(c, bq, q4);
        float a0, a1; rowsumsq(c, a0, a1);
        qn0 = sqrtf(a0); qn1 = sqrtf(a1);
        c2a(c, qah, qal);
    }
    __syncthreads();   // K, V tiles + wkm complete

    float kmax;
    {
        float m = wkm[0];
#pragma unroll
        for (int i = 1; i < 16; i++) m = fmaxf(m, wkm[i]);
        kmax = sqrtf(m);
    }
    // Flash loop (sync-free): safe max = ||q||*kmax/8 - 8 (keeps p in f16-normal range)
    float mr0 = qn0 * kmax * 0.125f - 8.0f;
    float mr1 = qn1 * kmax * 0.125f - 8.0f;
    float ov[8][4];
#pragma unroll
    for (int n = 0; n < 8; n++) { ov[n][0] = ov[n][1] = ov[n][2] = ov[n][3] = 0.f; }

#pragma unroll 1
    for (int sc = 0; sc < 4; sc++) {
        float s[8][4];
#pragma unroll
        for (int n = 0; n < 8; n++) { s[n][0] = s[n][1] = s[n][2] = s[n][3] = 0.f; }
        gemm64(s, qah, qal, sb + R_K, LOD_T, sc * 64, 0, ll, false);
#pragma unroll
        for (int n = 0; n < 8; n++) {
            s[n][0] = __expf(fmaf(s[n][0], 0.125f, -mr0));
            s[n][1] = __expf(fmaf(s[n][1], 0.125f, -mr0));
            s[n][2] = __expf(fmaf(s[n][2], 0.125f, -mr1));
            s[n][3] = __expf(fmaf(s[n][3], 0.125f, -mr1));
        }
        u32 ph[4][4], pl[4][4];
        c2a(s, ph, pl);
        gemm64(ov, ph, pl, sb + R_V, LOD_T, 0, sc * 64, ll, true);
    }

    // Epilogue: LN2 (regs) -> Wt GEMM -> LN3 + PReLU -> global
    float alv = __ldg(alpha);
    {
        float s0v, s1v, ss0, ss1;
        rowsum(ov, s0v, s1v);
        rowsumsq(ov, ss0, ss1);
        float mu0 = s0v * (1.0f / 64.0f), mu1 = s1v * (1.0f / 64.0f);
        float rs0 = rsqrtf(fmaxf(ss0 * (1.0f / 64.0f) - mu0 * mu0, 0.f) + 1e-12f);
        float rs1 = rsqrtf(fmaxf(ss1 * (1.0f / 64.0f) - mu1 * mu1, 0.f) + 1e-12f);
#pragma unroll
        for (int n = 0; n < 8; n++) {
            int c0i = 8 * n + 2 * q4;
            float2 g2v = *(const float2*)(g2 + c0i);
            float2 b2v = *(const float2*)(b2 + c0i);
            ov[n][0] = (ov[n][0] - mu0) * rs0 * g2v.x + b2v.x;
            ov[n][1] = (ov[n][1] - mu0) * rs0 * g2v.y + b2v.y;
            ov[n][2] = (ov[n][2] - mu1) * rs1 * g2v.x + b2v.x;
            ov[n][3] = (ov[n][3] - mu1) * rs1 * g2v.y + b2v.y;
        }
    }
    {
        u32 yh[4][4], yl[4][4];
        c2a(ov, yh, yl);
        float y[8][4];
#pragma unroll
        for (int n = 0; n < 8; n++) { y[n][0] = y[n][1] = y[n][2] = y[n][3] = 0.f; }
        gemm64(y, yh, yl, sb + R_WT, LOD_W, 0, 0, ll, false);
        addbias(y, bt, q4);
        float s0v, s1v, ss0, ss1;
        rowsum(y, s0v, s1v);
        rowsumsq(y, ss0, ss1);
        float mu0 = s0v * (1.0f / 64.0f), mu1 = s1v * (1.0f / 64.0f);
        float rs0 = rsqrtf(ss0 * (1.0f / 64.0f) - mu0 * mu0 + 1e-5f);
        float rs1 = rsqrtf(ss1 * (1.0f / 64.0f) - mu1 * mu1 + 1e-5f);
#pragma unroll
        for (int n = 0; n < 8; n++) {
            int c0i = 8 * n + 2 * q4;
            float2 g3v = *(const float2*)(g3 + c0i);
            float2 b3v = *(const float2*)(b3 + c0i);
            float e0 = (y[n][0] - mu0) * rs0 * g3v.x + b3v.x; e0 = e0 >= 0.f ? e0 : alv * e0;
            float e1 = (y[n][1] - mu0) * rs0 * g3v.y + b3v.y; e1 = e1 >= 0.f ? e1 : alv * e1;
            float e2 = (y[n][2] - mu1) * rs1 * g3v.x + b3v.x; e2 = e2 >= 0.f ? e2 : alv * e2;
            float e3 = (y[n][3] - mu1) * rs1 * g3v.y + b3v.y; e3 = e3 >= 0.f ? e3 : alv * e3;
            *(float2*)(xb + (m0 + g) * 64 + c0i)     = make_float2(e0, e1);
            *(float2*)(xb + (m0 + g + 8) * 64 + c0i) = make_float2(e2, e3);
        }
    }
}

// ---------------- launch ----------------
extern "C" void kernel_launch(void* const* d_in, const int* in_sizes, int n_in,
                              void* d_out, int out_size) {
    (void)in_sizes; (void)n_in; (void)out_size;
    const float* inputs = (const float*)d_in[0];
    const float* Wq = (const float*)d_in[1];  const float* bq = (const float*)d_in[2];
    const float* Wk = (const float*)d_in[3];  const float* bk = (const float*)d_in[4];
    const float* Wv = (const float*)d_in[5];  const float* bv = (const float*)d_in[6];
    const float* g1 = (const float*)d_in[7];  const float* b1 = (const float*)d_in[8];
    const float* g2 = (const float*)d_in[9];  const float* b2 = (const float*)d_in[10];
    const float* Wt = (const float*)d_in[11]; const float* bt = (const float*)d_in[12];
    const float* g3 = (const float*)d_in[13]; const float* b3 = (const float*)d_in[14];
    const float* alpha = (const float*)d_in[15];
    float* out = (float*)d_out;

    cudaFuncSetAttribute(k_attn, cudaFuncAttributeMaxDynamicSharedMemorySize, SMEM_BYTES);

    dim3 tgrid(8, 2, 8 * 256);
    dim3 tblk(32, 8);
    k_tin<<<tgrid, tblk>>>(inputs);
    k_attn<<<BB, 512, SMEM_BYTES>>>(Wq, bq, Wk, bk, Wv, bv, g1, b1, g2, b2,
                                    Wt, bt, g3, b3, alpha);
    k_tout<<<tgrid, tblk>>>(inputs, out);
}

// round 9
// speedup vs baseline: 3.1785x; 1.1019x over previous
#include <cuda_runtime.h>
#include <cstdint>

typedef uint32_t u32;
#define BB 2048

__device__ float g_scratch[(size_t)BB * 256 * 64];

// ---- smem map (bytes) ----
// Phase 1: R_H = H tile (hi @0, lo @32768), 64KB. After frag consumption the H
// region holds Wv@16384, Wq@32768, Wt@49152 (hi, lo at +8192 each).
// Wk lives in its own region so it can be staged BEFORE LN1.
#define R_H   0
#define R_WV  16384
#define R_WQ  32768
#define R_WT  49152
#define R_K   65536      // K tiles hi/lo (64KB)
#define R_V   131072     // V tiles hi/lo (64KB)
#define R_WKP 196608     // Wk hi @0, lo @+8192 (16KB, staged pre-LN1)
#define R_KM  212992     // 16 floats: per-warp max ||k||^2
#define SMEM_BYTES 213056
#define LOD_T 32768
#define LOD_W 8192

static __device__ __forceinline__ u32 s2u(const void* p) {
    u32 a;
    asm("{ .reg .u64 t; cvta.to.shared.u64 t, %1; cvt.u32.u64 %0, t; }" : "=r"(a) : "l"(p));
    return a;
}
static __device__ __forceinline__ u32 swz(u32 o) { return o ^ ((o >> 3) & 0x70); }

static __device__ __forceinline__ void ldm4(u32* r, u32 a) {
    asm volatile("ldmatrix.sync.aligned.m8n8.x4.shared.b16 {%0,%1,%2,%3},[%4];"
                 : "=r"(r[0]), "=r"(r[1]), "=r"(r[2]), "=r"(r[3]) : "r"(a));
}
static __device__ __forceinline__ void ldm2(u32* r, u32 a) {
    asm volatile("ldmatrix.sync.aligned.m8n8.x2.shared.b16 {%0,%1},[%2];"
                 : "=r"(r[0]), "=r"(r[1]) : "r"(a));
}
static __device__ __forceinline__ void ldm2t(u32* r, u32 a) {
    asm volatile("ldmatrix.sync.aligned.m8n8.x2.trans.shared.b16 {%0,%1},[%2];"
                 : "=r"(r[0]), "=r"(r[1]) : "r"(a));
}
static __device__ __forceinline__ void hmma(float* c, const u32* a, const u32* b) {
    asm volatile("mma.sync.aligned.m16n8k16.row.col.f32.f16.f16.f32 "
                 "{%0,%1,%2,%3},{%4,%5,%6,%7},{%8,%9},{%0,%1,%2,%3};"
                 : "+f"(c[0]), "+f"(c[1]), "+f"(c[2]), "+f"(c[3])
                 : "r"(a[0]), "r"(a[1]), "r"(a[2]), "r"(a[3]), "r"(b[0]), "r"(b[1]));
}
static __device__ __forceinline__ u32 f16pk(float a, float b) {   // a -> low half
    u32 r; asm("cvt.rn.f16x2.f32 %0,%1,%2;" : "=r"(r) : "f"(b), "f"(a)); return r;
}
static __device__ __forceinline__ void h2up(u32 h, float& a, float& b) {
    asm("{.reg .b16 l,hh; mov.b32 {l,hh},%2; cvt.f32.f16 %0,l; cvt.f32.f16 %1,hh;}"
        : "=f"(a), "=f"(b) : "r"(h));
}
static __device__ __forceinline__ void split2(float a, float b, u32& hi, u32& lo) {
    u32 h = f16pk(a, b); float fa, fb; h2up(h, fa, fb);
    hi = h; lo = f16pk(a - fa, b - fb);
}
static __device__ __forceinline__ void st32(u32 a, u32 v) {
    asm volatile("st.shared.b32 [%0],%1;" :: "r"(a), "r"(v) : "memory");
}

// 3-term 64-col GEMM (paired-n interleave, batched LDSM).
static __device__ __forceinline__ void gemm64(float (*c)[4],
        const u32 (*ah)[4], const u32 (*al)[4],
        u32 bbase, u32 lod, int n0, int k0, int ll, bool trans) {
#pragma unroll
    for (int np = 0; np < 4; np++) {
#pragma unroll
        for (int k = 0; k < 4; k++) {
            u32 offA, offB;
            if (!trans) {
                offA = (u32)(n0 + 16 * np + (ll & 7)) * 128 + (u32)(k0 + 16 * k) * 2 + ((ll >> 3) & 1) * 16;
                offB = offA + 8 * 128;
            } else {
                offA = (u32)(k0 + 16 * k + ((ll >> 3) & 1) * 8 + (ll & 7)) * 128 + (u32)(32 * np);
                offB = offA + 16;
            }
            u32 aA = bbase + swz(offA), aB = bbase + swz(offB);
            u32 bhA[2], blA[2], bhB[2], blB[2];
            if (trans) { ldm2t(bhA, aA); ldm2t(bhB, aB); ldm2t(blA, aA + lod); ldm2t(blB, aB + lod); }
            else       { ldm2(bhA, aA);  ldm2(bhB, aB);  ldm2(blA, aA + lod);  ldm2(blB, aB + lod); }
            hmma(c[2 * np], ah[k], bhA); hmma(c[2 * np + 1], ah[k], bhB);
            hmma(c[2 * np], ah[k], blA); hmma(c[2 * np + 1], ah[k], blB);
            hmma(c[2 * np], al[k], bhA); hmma(c[2 * np + 1], al[k], bhB);
        }
    }
}
// 2-term variant: A hi only (A effectively rounded to f16), B still hi+lo.
static __device__ __forceinline__ void gemm64_2(float (*c)[4],
        const u32 (*ah)[4],
        u32 bbase, u32 lod, int n0, int k0, int ll, bool trans) {
#pragma unroll
    for (int np = 0; np < 4; np++) {
#pragma unroll
        for (int k = 0; k < 4; k++) {
            u32 offA, offB;
            if (!trans) {
                offA = (u32)(n0 + 16 * np + (ll & 7)) * 128 + (u32)(k0 + 16 * k) * 2 + ((ll >> 3) & 1) * 16;
                offB = offA + 8 * 128;
            } else {
                offA = (u32)(k0 + 16 * k + ((ll >> 3) & 1) * 8 + (ll & 7)) * 128 + (u32)(32 * np);
                offB = offA + 16;
            }
            u32 aA = bbase + swz(offA), aB = bbase + swz(offB);
            u32 bhA[2], blA[2], bhB[2], blB[2];
            if (trans) { ldm2t(bhA, aA); ldm2t(bhB, aB); ldm2t(blA, aA + lod); ldm2t(blB, aB + lod); }
            else       { ldm2(bhA, aA);  ldm2(bhB, aB);  ldm2(blA, aA + lod);  ldm2(blB, aB + lod); }
            hmma(c[2 * np], ah[k], bhA); hmma(c[2 * np + 1], ah[k], bhB);
            hmma(c[2 * np], ah[k], blA); hmma(c[2 * np + 1], ah[k], blB);
        }
    }
}
// C-frag (m16 x 64) -> A-frag hi/lo
static __device__ __forceinline__ void c2a(const float (*c)[4], u32 (*fh)[4], u32 (*fl)[4]) {
#pragma unroll
    for (int kk = 0; kk < 4; kk++) {
        split2(c[2 * kk][0],     c[2 * kk][1],     fh[kk][0], fl[kk][0]);
        split2(c[2 * kk][2],     c[2 * kk][3],     fh[kk][1], fl[kk][1]);
        split2(c[2 * kk + 1][0], c[2 * kk + 1][1], fh[kk][2], fl[kk][2]);
        split2(c[2 * kk + 1][2], c[2 * kk + 1][3], fh[kk][3], fl[kk][3]);
    }
}
// C-frag -> A-frag hi only
static __device__ __forceinline__ void c2a_hi(const float (*c)[4], u32 (*fh)[4]) {
#pragma unroll
    for (int kk = 0; kk < 4; kk++) {
        fh[kk][0] = f16pk(c[2 * kk][0],     c[2 * kk][1]);
        fh[kk][1] = f16pk(c[2 * kk][2],     c[2 * kk][3]);
        fh[kk][2] = f16pk(c[2 * kk + 1][0], c[2 * kk + 1][1]);
        fh[kk][3] = f16pk(c[2 * kk + 1][2], c[2 * kk + 1][3]);
    }
}
static __device__ __forceinline__ void addbias(float (*c)[4], const float* __restrict__ bias, int q4) {
#pragma unroll
    for (int n = 0; n < 8; n++) {
        float b0 = bias[8 * n + 2 * q4], b1 = bias[8 * n + 2 * q4 + 1];
        c[n][0] += b0; c[n][1] += b1; c[n][2] += b0; c[n][3] += b1;
    }
}
static __device__ __forceinline__ void cstore16(const float (*c)[4], u32 base, int m0, int lane) {
    int g = lane >> 2, q4 = lane & 3;
#pragma unroll
    for (int n = 0; n < 8; n++) {
        u32 o0 = swz((u32)(m0 + g) * 128 + 16 * n + 4 * q4);
        u32 o1 = swz((u32)(m0 + g + 8) * 128 + 16 * n + 4 * q4);
        u32 h0, l0, h1, l1;
        split2(c[n][0], c[n][1], h0, l0);
        split2(c[n][2], c[n][3], h1, l1);
        st32(base + o0, h0); st32(base + LOD_T + o0, l0);
        st32(base + o1, h1); st32(base + LOD_T + o1, l1);
    }
}
static __device__ __forceinline__ void rowsum(const float (*c)[4], float& r0, float& r1) {
    float s0 = 0.f, s1 = 0.f;
#pragma unroll
    for (int n = 0; n < 8; n++) { s0 += c[n][0] + c[n][1]; s1 += c[n][2] + c[n][3]; }
    s0 += __shfl_xor_sync(~0u, s0, 1); s0 += __shfl_xor_sync(~0u, s0, 2);
    s1 += __shfl_xor_sync(~0u, s1, 1); s1 += __shfl_xor_sync(~0u, s1, 2);
    r0 = s0; r1 = s1;
}
static __device__ __forceinline__ void rowsumsq(const float (*c)[4], float& r0, float& r1) {
    float s0 = 0.f, s1 = 0.f;
#pragma unroll
    for (int n = 0; n < 8; n++) {
        s0 += c[n][0] * c[n][0] + c[n][1] * c[n][1];
        s1 += c[n][2] * c[n][2] + c[n][3] * c[n][3];
    }
    s0 += __shfl_xor_sync(~0u, s0, 1); s0 += __shfl_xor_sync(~0u, s0, 2);
    s1 += __shfl_xor_sync(~0u, s1, 1); s1 += __shfl_xor_sync(~0u, s1, 2);
    r0 = s0; r1 = s1;
}
static __device__ __forceinline__ void stageW(const float* __restrict__ W, u32 base, int tid) {
    for (int i = tid; i < 2048; i += 512) {
        int r = i >> 5, c2 = (i & 31) * 2;
        float2 w = *(const float2*)(W + r * 64 + c2);
        u32 h, l; split2(w.x, w.y, h, l);
        u32 o = swz((u32)r * 128 + (u32)c2 * 2);
        st32(base + o, h); st32(base + LOD_W + o, l);
    }
}

// ---------------- transposes (float4, 128-wide t tiles) ----------------
// grid (2, 2, 2048), block 256. tile = 32 c x 128 t.
__global__ void k_tin(const float* __restrict__ in) {
    __shared__ float tile[32][129];
    int n = blockIdx.z >> 8, f = blockIdx.z & 255;
    int c0 = blockIdx.y << 5, t0 = blockIdx.x << 7;
    int j = threadIdx.x;
    int tr = j & 31, cr = j >> 5;
    size_t base_in = ((size_t)(n * 64 + c0) * 256 + f) * 256 + t0;
#pragma unroll
    for (int p = 0; p < 4; p++) {
        int c = cr + p * 8;
        float4 v = *(const float4*)(in + base_in + (size_t)c * 65536 + 4 * tr);
        tile[c][4 * tr] = v.x; tile[c][4 * tr + 1] = v.y;
        tile[c][4 * tr + 2] = v.z; tile[c][4 * tr + 3] = v.w;
    }
    __syncthreads();
    int cw = (j & 7) * 4, trw = j >> 3;
    size_t base_out = (size_t)(n * 256) * 16384 + (size_t)f * 64 + c0;
#pragma unroll
    for (int p = 0; p < 4; p++) {
        int t = trw + p * 32;
        float4 v = make_float4(tile[cw][t], tile[cw + 1][t], tile[cw + 2][t], tile[cw + 3][t]);
        *(float4*)(g_scratch + base_out + (size_t)(t0 + t) * 16384 + cw) = v;
    }
}
__global__ void k_tout(const float* __restrict__ in, float* __restrict__ out) {
    __shared__ float tile[32][129];
    int n = blockIdx.z >> 8, f = blockIdx.z & 255;
    int c0 = blockIdx.y << 5, t0 = blockIdx.x << 7;
    int j = threadIdx.x;
    int cw = (j & 7) * 4, trw = j >> 3;
    size_t base_y = (size_t)(n * 256) * 16384 + (size_t)f * 64 + c0;
#pragma unroll
    for (int p = 0; p < 4; p++) {
        int t = trw + p * 32;
        float4 v = *(const float4*)(g_scratch + base_y + (size_t)(t0 + t) * 16384 + cw);
        tile[cw][t] = v.x; tile[cw + 1][t] = v.y; tile[cw + 2][t] = v.z; tile[cw + 3][t] = v.w;
    }
    __syncthreads();
    int tr = j & 31, cr = j >> 5;
    size_t base_o = ((size_t)(n * 64 + c0) * 256 + f) * 256 + t0;
#pragma unroll
    for (int p = 0; p < 4; p++) {
        int c = cr + p * 8;
        size_t a = base_o + (size_t)c * 65536 + 4 * tr;
        float4 r = *(const float4*)(in + a);
        r.x += tile[c][4 * tr];     r.y += tile[c][4 * tr + 1];
        r.z += tile[c][4 * tr + 2]; r.w += tile[c][4 * tr + 3];
        *(float4*)(out + a) = r;
    }
}

// ---------------- fused attention (mma.sync, 512 threads, 16 rows/warp) ----------------
__global__ void __launch_bounds__(512, 1) k_attn(
    const float* __restrict__ Wq, const float* __restrict__ bq,
    const float* __restrict__ Wk, const float* __restrict__ bk,
    const float* __restrict__ Wv, const float* __restrict__ bv,
    const float* __restrict__ g1, const float* __restrict__ b1,
    const float* __restrict__ g2, const float* __restrict__ b2,
    const float* __restrict__ Wt, const float* __restrict__ bt,
    const float* __restrict__ g3, const float* __restrict__ b3,
    const float* __restrict__ alpha)
{
    extern __shared__ char smem[];
    u32 sb = s2u(smem);
    float* wkm = (float*)(smem + R_KM);
    int tid = threadIdx.x, lane = tid & 31, wrp = tid >> 5;
    int g = lane >> 2, q4 = lane & 3, ll = lane & 15;
    int m0 = wrp * 16;
    float* xb = g_scratch + (size_t)blockIdx.x * 16384;

    // Stage Wk into its dedicated region first (loads overlap LN1's x loads)
    stageW(Wk, sb + R_WKP, tid);

    // Phase 0: LN1 (warp per row, 16 warps) -> H hi/lo tiles
    {
        float2 g1v = ((const float2*)g1)[lane];
        float2 b1v = ((const float2*)b1)[lane];
        for (int r = wrp; r < 256; r += 16) {
            float2 x = *(const float2*)(xb + r * 64 + 2 * lane);
            float s = x.x + x.y;
#pragma unroll
            for (int o = 16; o; o >>= 1) s += __shfl_xor_sync(~0u, s, o);
            float mean = s * (1.0f / 64.0f);
            float d0 = x.x - mean, d1 = x.y - mean;
            float v = d0 * d0 + d1 * d1;
#pragma unroll
            for (int o = 16; o; o >>= 1) v += __shfl_xor_sync(~0u, v, o);
            float rs = rsqrtf(v * (1.0f / 64.0f) + 1e-5f);
            u32 h, l; split2(d0 * rs * g1v.x + b1v.x, d1 * rs * g1v.y + b1v.y, h, l);
            u32 o = swz((u32)r * 128 + (u32)lane * 4);
            st32(sb + R_H + o, h); st32(sb + R_H + LOD_T + o, l);
        }
    }
    __syncthreads();

    // H A-fragments for this warp's 16 rows
    u32 hah[4][4], hal[4][4];
#pragma unroll
    for (int k = 0; k < 4; k++) {
        u32 o = swz((u32)(m0 + (lane & 15)) * 128 + (u32)k * 32 + ((lane >> 4) & 1) * 16);
        ldm4(hah[k], sb + R_H + o);
        ldm4(hal[k], sb + R_H + LOD_T + o);
    }
    __syncthreads();   // H tiles fully consumed -> region becomes weight storage

    // Prefetch Wv/Wq/Wt into registers (latency hidden behind K projection)
    float2 wv_r[4], wq_r[4], wt_r[4];
#pragma unroll
    for (int it = 0; it < 4; it++) {
        int i = tid + it * 512;
        int r = i >> 5, c2 = (i & 31) * 2;
        wv_r[it] = *(const float2*)(Wv + r * 64 + c2);
        wq_r[it] = *(const float2*)(Wq + r * 64 + c2);
        wt_r[it] = *(const float2*)(Wt + r * 64 + c2);
    }

    // K projection (Wk preloaded) -> K tiles + max||k||^2
    {
        float c[8][4];
#pragma unroll
        for (int n = 0; n < 8; n++) { c[n][0] = c[n][1] = c[n][2] = c[n][3] = 0.f; }
        gemm64(c, hah, hal, sb + R_WKP, LOD_W, 0, 0, ll, false);
        addbias(c, bk, q4);
        float a0, a1; rowsumsq(c, a0, a1);
        float kmx = fmaxf(a0, a1);
#pragma unroll
        for (int o = 16; o; o >>= 1) kmx = fmaxf(kmx, __shfl_xor_sync(~0u, kmx, o));
        if (lane == 0) wkm[wrp] = kmx;
        cstore16(c, sb + R_K, m0, lane);
    }
    // Store prefetched weights into the dead H region
#pragma unroll
    for (int it = 0; it < 4; it++) {
        int i = tid + it * 512;
        int r = i >> 5, c2 = (i & 31) * 2;
        u32 o = swz((u32)r * 128 + (u32)c2 * 2);
        u32 h, l;
        split2(wv_r[it].x, wv_r[it].y, h, l); st32(sb + R_WV + o, h); st32(sb + R_WV + LOD_W + o, l);
        split2(wq_r[it].x, wq_r[it].y, h, l); st32(sb + R_WQ + o, h); st32(sb + R_WQ + LOD_W + o, l);
        split2(wt_r[it].x, wt_r[it].y, h, l); st32(sb + R_WT + o, h); st32(sb + R_WT + LOD_W + o, l);
    }
    __syncthreads();

    // V projection -> V tiles
    {
        float c[8][4];
#pragma unroll
        for (int n = 0; n < 8; n++) { c[n][0] = c[n][1] = c[n][2] = c[n][3] = 0.f; }
        gemm64(c, hah, hal, sb + R_WV, LOD_W, 0, 0, ll, false);
        addbias(c, bv, q4);
        cstore16(c, sb + R_V, m0, lane);
    }
    // Q projection -> A-fragments (registers only) + ||q|| (regs)
    u32 qah[4][4], qal[4][4];
    float qn0, qn1;
    {
        float c[8][4];
#pragma unroll
        for (int n = 0; n < 8; n++) { c[n][0] = c[n][1] = c[n][2] = c[n][3] = 0.f; }
        gemm64(c, hah, hal, sb + R_WQ, LOD_W, 0, 0, ll, false);
        addbias(c, bq, q4);
        float a0, a1; rowsumsq(c, a0, a1);
        qn0 = sqrtf(a0); qn1 = sqrtf(a1);
        c2a(c, qah, qal);
    }
    __syncthreads();   // K, V tiles + wkm complete

    float kmax;
    {
        float m = wkm[0];
#pragma unroll
        for (int i = 1; i < 16; i++) m = fmaxf(m, wkm[i]);
        kmax = sqrtf(m);
    }
    // Flash loop (sync-free): safe max = ||q||*kmax/8 - 8 (keeps p in f16-normal range)
    float mr0 = qn0 * kmax * 0.125f - 8.0f;
    float mr1 = qn1 * kmax * 0.125f - 8.0f;
    float ov[8][4];
#pragma unroll
    for (int n = 0; n < 8; n++) { ov[n][0] = ov[n][1] = ov[n][2] = ov[n][3] = 0.f; }

#pragma unroll 1
    for (int sc = 0; sc < 4; sc++) {
        float s[8][4];
#pragma unroll
        for (int n = 0; n < 8; n++) { s[n][0] = s[n][1] = s[n][2] = s[n][3] = 0.f; }
        gemm64(s, qah, qal, sb + R_K, LOD_T, sc * 64, 0, ll, false);
#pragma unroll
        for (int n = 0; n < 8; n++) {
            s[n][0] = __expf(fmaf(s[n][0], 0.125f, -mr0));
            s[n][1] = __expf(fmaf(s[n][1], 0.125f, -mr0));
            s[n][2] = __expf(fmaf(s[n][2], 0.125f, -mr1));
            s[n][3] = __expf(fmaf(s[n][3], 0.125f, -mr1));
        }
        u32 ph[4][4];
        c2a_hi(s, ph);                    // P rounded to f16 (lo term dropped: ~2.4e-4)
        gemm64_2(ov, ph, sb + R_V, LOD_T, 0, sc * 64, ll, true);
    }

    // Epilogue: LN2 (regs) -> Wt GEMM (2-term) -> LN3 + PReLU -> global
    float alv = __ldg(alpha);
    {
        float s0v, s1v, ss0, ss1;
        rowsum(ov, s0v, s1v);
        rowsumsq(ov, ss0, ss1);
        float mu0 = s0v * (1.0f / 64.0f), mu1 = s1v * (1.0f / 64.0f);
        float rs0 = rsqrtf(fmaxf(ss0 * (1.0f / 64.0f) - mu0 * mu0, 0.f) + 1e-12f);
        float rs1 = rsqrtf(fmaxf(ss1 * (1.0f / 64.0f) - mu1 * mu1, 0.f) + 1e-12f);
#pragma unroll
        for (int n = 0; n < 8; n++) {
            int c0i = 8 * n + 2 * q4;
            float2 g2v = *(const float2*)(g2 + c0i);
            float2 b2v = *(const float2*)(b2 + c0i);
            ov[n][0] = (ov[n][0] - mu0) * rs0 * g2v.x + b2v.x;
            ov[n][1] = (ov[n][1] - mu0) * rs0 * g2v.y + b2v.y;
            ov[n][2] = (ov[n][2] - mu1) * rs1 * g2v.x + b2v.x;
            ov[n][3] = (ov[n][3] - mu1) * rs1 * g2v.y + b2v.y;
        }
    }
    {
        u32 yh[4][4];
        c2a_hi(ov, yh);                   // LN2 output rounded to f16 (~1.5e-4)
        float y[8][4];
#pragma unroll
        for (int n = 0; n < 8; n++) { y[n][0] = y[n][1] = y[n][2] = y[n][3] = 0.f; }
        gemm64_2(y, yh, sb + R_WT, LOD_W, 0, 0, ll, false);
        addbias(y, bt, q4);
        float s0v, s1v, ss0, ss1;
        rowsum(y, s0v, s1v);
        rowsumsq(y, ss0, ss1);
        float mu0 = s0v * (1.0f / 64.0f), mu1 = s1v * (1.0f / 64.0f);
        float rs0 = rsqrtf(ss0 * (1.0f / 64.0f) - mu0 * mu0 + 1e-5f);
        float rs1 = rsqrtf(ss1 * (1.0f / 64.0f) - mu1 * mu1 + 1e-5f);
#pragma unroll
        for (int n = 0; n < 8; n++) {
            int c0i = 8 * n + 2 * q4;
            float2 g3v = *(const float2*)(g3 + c0i);
            float2 b3v = *(const float2*)(b3 + c0i);
            float e0 = (y[n][0] - mu0) * rs0 * g3v.x + b3v.x; e0 = e0 >= 0.f ? e0 : alv * e0;
            float e1 = (y[n][1] - mu0) * rs0 * g3v.y + b3v.y; e1 = e1 >= 0.f ? e1 : alv * e1;
            float e2 = (y[n][2] - mu1) * rs1 * g3v.x + b3v.x; e2 = e2 >= 0.f ? e2 : alv * e2;
            float e3 = (y[n][3] - mu1) * rs1 * g3v.y + b3v.y; e3 = e3 >= 0.f ? e3 : alv * e3;
            *(float2*)(xb + (m0 + g) * 64 + c0i)     = make_float2(e0, e1);
            *(float2*)(xb + (m0 + g + 8) * 64 + c0i) = make_float2(e2, e3);
        }
    }
}

// ---------------- launch ----------------
extern "C" void kernel_launch(void* const* d_in, const int* in_sizes, int n_in,
                              void* d_out, int out_size) {
    (void)in_sizes; (void)n_in; (void)out_size;
    const float* inputs = (const float*)d_in[0];
    const float* Wq = (const float*)d_in[1];  const float* bq = (const float*)d_in[2];
    const float* Wk = (const float*)d_in[3];  const float* bk = (const float*)d_in[4];
    const float* Wv = (const float*)d_in[5];  const float* bv = (const float*)d_in[6];
    const float* g1 = (const float*)d_in[7];  const float* b1 = (const float*)d_in[8];
    const float* g2 = (const float*)d_in[9];  const float* b2 = (const float*)d_in[10];
    const float* Wt = (const float*)d_in[11]; const float* bt = (const float*)d_in[12];
    const float* g3 = (const float*)d_in[13]; const float* b3 = (const float*)d_in[14];
    const float* alpha = (const float*)d_in[15];
    float* out = (float*)d_out;

    cudaFuncSetAttribute(k_attn, cudaFuncAttributeMaxDynamicSharedMemorySize, SMEM_BYTES);

    dim3 tgrid(2, 2, 8 * 256);
    k_tin<<<tgrid, 256>>>(inputs);
    k_attn<<<BB, 512, SMEM_BYTES>>>(Wq, bq, Wk, bk, Wv, bv, g1, b1, g2, b2,
                                    Wt, bt, g3, b3, alpha);
    k_tout<<<tgrid, 256>>>(inputs, out);
}